// round 9
// baseline (speedup 1.0000x reference)
#include <cuda_runtime.h>
#include <math.h>
#include <stdint.h>

// ---------------------------------------------------------------------------
// Problem constants (fixed by setup_inputs)
#define BB   2
#define TT   2048
#define DIMC 1024
#define HH   16
#define DHH  64
#define LL   3
#define KKS  4
#define TOTROWS 7168           // 4096 + 2048 + 1024 rows of K/V

// GEMM tiling: 128x256 CTA tile, BK=32, 3-stage cp.async, 16 warps (32x64 each)
#define BM 128
#define BN 256
#define BK 32
#define NSTAGE 3
#define NT (DIMC / BK)          // 32 k-iterations
#define ROWF 36                 // smem row stride in floats (144B)
#define TILEFA (BM * ROWF)      // 4608 floats
#define TILEFB (BN * ROWF)      // 9216 floats
#define STAGEF (TILEFA + TILEFB)
#define GEMM_SMEM (NSTAGE * STAGEF * 4)   // 165888 bytes

// ---------------------------------------------------------------------------
// scratch (device globals; no allocation allowed)
__device__ float g_xr    [BB * TT * DIMC];           // tf32-rounded x
__device__ float g_q     [BB * TT * DIMC];
__device__ float g_off   [BB * TT * HH * LL * KKS];
__device__ float g_k     [TOTROWS * DIMC];
__device__ float g_v     [TOTROWS * DIMC];
__device__ float g_ao    [BB * TT * DIMC];
__device__ float g_WqkvoT[4 * DIMC * DIMC];          // [Wq;Wk;Wv;Wo] transposed [N,K]

// ---------------------------------------------------------------------------
__device__ __forceinline__ float rna_tf32(float x) {
    float r;
    asm("cvt.rna.tf32.f32 %0, %1;" : "=f"(r) : "f"(x));
    return r;
}
__device__ __forceinline__ uint32_t smem_u32(const void* p) {
    uint32_t a;
    asm("{ .reg .u64 t; cvta.to.shared.u64 t, %1; cvt.u32.u64 %0, t; }"
        : "=r"(a) : "l"(p));
    return a;
}
__device__ __forceinline__ void cp_async16(uint32_t dst, const void* src) {
    asm volatile("cp.async.cg.shared.global [%0], [%1], 16;"
                 :: "r"(dst), "l"(src) : "memory");
}
__device__ __forceinline__ void cp_commit() {
    asm volatile("cp.async.commit_group;" ::: "memory");
}
template <int N>
__device__ __forceinline__ void cp_wait() {
    asm volatile("cp.async.wait_group %0;" :: "n"(N) : "memory");
}
__device__ __forceinline__ void mma_tf32(float& d0, float& d1, float& d2, float& d3,
                                         uint32_t a0, uint32_t a1, uint32_t a2, uint32_t a3,
                                         uint32_t b0, uint32_t b1) {
    asm volatile(
        "mma.sync.aligned.m16n8k8.row.col.f32.tf32.tf32.f32 "
        "{%0,%1,%2,%3}, {%4,%5,%6,%7}, {%8,%9}, {%0,%1,%2,%3};"
        : "+f"(d0), "+f"(d1), "+f"(d2), "+f"(d3)
        : "r"(a0), "r"(a1), "r"(a2), "r"(a3), "r"(b0), "r"(b1));
}

// ---------------------------------------------------------------------------
// tf32 mma.sync GEMM, 128x256 tile, 512 threads (16 warps, 4x4 grid,
// 32x64 warp tiles), segmented output routing. 4 warps/SMSP for latency hiding.
__global__ __launch_bounds__(512, 1) void gemm_tf32(
    const float* __restrict__ A, const float* __restrict__ BT,
    const float* __restrict__ b0, const float* __restrict__ b1,
    const float* __restrict__ b2,
    float* __restrict__ C0, float* __restrict__ C1, float* __restrict__ C2) {
    extern __shared__ float smem[];

    int tid  = threadIdx.x;
    int wid  = tid >> 5, lane = tid & 31;
    int gid  = lane >> 2, tg = lane & 3;
    int wm   = wid >> 2;          // 0..3 (32-row band)
    int wn   = wid & 3;           // 0..3 (64-col band)
    int m0   = blockIdx.y * BM;

    int seg  = blockIdx.x >> 2;
    int ncol = (blockIdx.x & 3) * BN;
    const float* bias = (seg == 0) ? b0 : (seg == 1) ? b1 : b2;
    float* C          = (seg == 0) ? C0 : (seg == 1) ? C1 : C2;

    uint32_t sbase = smem_u32(smem);

    const float* Abase = A  + (size_t)m0 * DIMC;
    const float* Bbase = BT + (size_t)blockIdx.x * BN * DIMC;

    float acc[2][8][4];
#pragma unroll
    for (int mi = 0; mi < 2; mi++)
#pragma unroll
        for (int ni = 0; ni < 8; ni++)
#pragma unroll
            for (int r = 0; r < 4; r++) acc[mi][ni][r] = 0.f;

    // per-stage async copy: A tile 2 chunks/thread, B tile 4 chunks/thread
#define ISSUE_STAGE(pt) do {                                                   \
        uint32_t sa_  = sbase + (((pt) % NSTAGE) * STAGEF) * 4;                \
        uint32_t sbB_ = sa_ + TILEFA * 4;                                      \
        _Pragma("unroll")                                                      \
        for (int i_ = 0; i_ < 2; i_++) {                                       \
            int cid_ = i_ * 512 + tid;                                         \
            int r_ = cid_ >> 3, c_ = cid_ & 7;                                 \
            cp_async16(sa_ + (r_ * ROWF + c_ * 4) * 4,                         \
                       Abase + (size_t)r_ * DIMC + (pt) * BK + c_ * 4);        \
        }                                                                      \
        _Pragma("unroll")                                                      \
        for (int i_ = 0; i_ < 4; i_++) {                                       \
            int cid_ = i_ * 512 + tid;                                         \
            int r_ = cid_ >> 3, c_ = cid_ & 7;                                 \
            cp_async16(sbB_ + (r_ * ROWF + c_ * 4) * 4,                        \
                       Bbase + (size_t)r_ * DIMC + (pt) * BK + c_ * 4);        \
        }                                                                      \
        cp_commit();                                                           \
    } while (0)

    ISSUE_STAGE(0);
    ISSUE_STAGE(1);

    for (int kt = 0; kt < NT; kt++) {
        if (kt + 2 < NT) cp_wait<1>(); else cp_wait<0>();
        __syncthreads();   // stage kt visible AND stage (kt+2)%3 free

        if (kt + 2 < NT) ISSUE_STAGE(kt + 2);

        const uint32_t* Au = (const uint32_t*)(smem + (kt % NSTAGE) * STAGEF);
        const uint32_t* Bu = Au + TILEFA;

#pragma unroll
        for (int j = 0; j < 4; j++) {
            uint32_t af[2][4], bf[8][2];
            int kb = j * 8 + tg;
#pragma unroll
            for (int mi = 0; mi < 2; mi++) {
                int mrow = wm * 32 + mi * 16 + gid;
                af[mi][0] = Au[mrow * ROWF + kb];
                af[mi][1] = Au[(mrow + 8) * ROWF + kb];
                af[mi][2] = Au[mrow * ROWF + kb + 4];
                af[mi][3] = Au[(mrow + 8) * ROWF + kb + 4];
            }
#pragma unroll
            for (int ni = 0; ni < 8; ni++) {
                int nrow = wn * 64 + ni * 8 + gid;
                bf[ni][0] = Bu[nrow * ROWF + kb];
                bf[ni][1] = Bu[nrow * ROWF + kb + 4];
            }
#pragma unroll
            for (int mi = 0; mi < 2; mi++)
#pragma unroll
                for (int ni = 0; ni < 8; ni++)
                    mma_tf32(acc[mi][ni][0], acc[mi][ni][1],
                             acc[mi][ni][2], acc[mi][ni][3],
                             af[mi][0], af[mi][1], af[mi][2], af[mi][3],
                             bf[ni][0], bf[ni][1]);
        }
    }

#pragma unroll
    for (int mi = 0; mi < 2; mi++) {
        int r0 = m0 + wm * 32 + mi * 16 + gid;
#pragma unroll
        for (int ni = 0; ni < 8; ni++) {
            int c = ncol + wn * 64 + ni * 8 + tg * 2;
            float bx = bias[c], by = bias[c + 1];
            float2 o0 = make_float2(acc[mi][ni][0] + bx, acc[mi][ni][1] + by);
            float2 o1 = make_float2(acc[mi][ni][2] + bx, acc[mi][ni][3] + by);
            *(float2*)&C[(size_t)r0 * DIMC + c] = o0;
            *(float2*)&C[(size_t)(r0 + 8) * DIMC + c] = o1;
        }
    }
#undef ISSUE_STAGE
}

// ---------------------------------------------------------------------------
// fp32 SGEMM (exact) for the offset projection: C[M,N] = A@W + bias, N=192
__global__ __launch_bounds__(256) void sgemm_bias(
    int M, int N, int K,
    const float* __restrict__ A, const float* __restrict__ W,
    const float* __restrict__ bias, float* __restrict__ C) {
    __shared__ float As[8][128];
    __shared__ float Bs[8][128];

    int tid = threadIdx.x;
    int bm = blockIdx.y, bn = blockIdx.x;

    int aRow = tid >> 1;
    int aCol = (tid & 1) * 4;
    int bRow = tid >> 5;
    int bCol = (tid & 31) * 4;
    int wcol = bn * 128 + bCol;

    int tRow = (tid >> 4) * 8;
    int tCol = (tid & 15) * 8;

    const float* Ab = A + (size_t)(bm * 128 + aRow) * K + aCol;

    float acc[8][8];
#pragma unroll
    for (int i = 0; i < 8; i++)
#pragma unroll
        for (int j = 0; j < 8; j++) acc[i][j] = 0.f;

    for (int k0 = 0; k0 < K; k0 += 8) {
        float4 av = *(const float4*)(Ab + k0);
        As[aCol + 0][aRow] = av.x;
        As[aCol + 1][aRow] = av.y;
        As[aCol + 2][aRow] = av.z;
        As[aCol + 3][aRow] = av.w;
        float4 wv = make_float4(0.f, 0.f, 0.f, 0.f);
        if (wcol < N)
            wv = *(const float4*)(W + (size_t)(k0 + bRow) * N + wcol);
        *(float4*)&Bs[bRow][bCol] = wv;
        __syncthreads();
#pragma unroll
        for (int kk = 0; kk < 8; kk++) {
            float4 a0 = *(const float4*)&As[kk][tRow];
            float4 a1 = *(const float4*)&As[kk][tRow + 4];
            float4 b0 = *(const float4*)&Bs[kk][tCol];
            float4 b1 = *(const float4*)&Bs[kk][tCol + 4];
            float av8[8] = {a0.x, a0.y, a0.z, a0.w, a1.x, a1.y, a1.z, a1.w};
            float bv8[8] = {b0.x, b0.y, b0.z, b0.w, b1.x, b1.y, b1.z, b1.w};
#pragma unroll
            for (int i = 0; i < 8; i++)
#pragma unroll
                for (int j = 0; j < 8; j++) acc[i][j] += av8[i] * bv8[j];
        }
        __syncthreads();
    }

#pragma unroll
    for (int i = 0; i < 8; i++) {
        size_t row = (size_t)(bm * 128 + tRow + i);
#pragma unroll
        for (int j = 0; j < 8; j += 4) {
            int col = bn * 128 + tCol + j;
            if (col < N) {
                float4 o;
                o.x = acc[i][j + 0] + bias[col + 0];
                o.y = acc[i][j + 1] + bias[col + 1];
                o.z = acc[i][j + 2] + bias[col + 2];
                o.w = acc[i][j + 3] + bias[col + 3];
                *(float4*)&C[row * N + col] = o;
            }
        }
    }
}

// ---------------------------------------------------------------------------
__global__ void rna_copy(const float4* __restrict__ in, float4* __restrict__ out, int n4) {
    int i = blockIdx.x * blockDim.x + threadIdx.x;
    if (i >= n4) return;
    float4 v = in[i];
    v.x = rna_tf32(v.x); v.y = rna_tf32(v.y);
    v.z = rna_tf32(v.z); v.w = rna_tf32(v.w);
    out[i] = v;
}

// row-pair average on K/V (downsample commutes with linear projection)
__global__ void downsample_kernel(const float* __restrict__ in,
                                  float* __restrict__ out, int Tout) {
    int i = blockIdx.x * blockDim.x + threadIdx.x;
    int c4 = i % (DIMC / 4);
    int t  = (i / (DIMC / 4)) % Tout;
    int b  = i / (Tout * (DIMC / 4));
    if (b >= BB) return;
    const float4* in4 = (const float4*)in;
    float4 a = in4[((size_t)b * 2 * Tout + 2 * t)     * (DIMC / 4) + c4];
    float4 c = in4[((size_t)b * 2 * Tout + 2 * t + 1) * (DIMC / 4) + c4];
    float4 r;
    r.x = 0.5f * (a.x + c.x);
    r.y = 0.5f * (a.y + c.y);
    r.z = 0.5f * (a.z + c.z);
    r.w = 0.5f * (a.w + c.w);
    ((float4*)out)[i] = r;
}

// fused transpose + tf32 round for 4 weights: WT[z][n][k] = rna(W_z[k][n])
__global__ void transpose_rna4(const float* __restrict__ W0, const float* __restrict__ W1,
                               const float* __restrict__ W2, const float* __restrict__ W3,
                               float* __restrict__ WT) {
    __shared__ float tile[32][33];
    int z  = blockIdx.z;
    const float* W = (z == 0) ? W0 : (z == 1) ? W1 : (z == 2) ? W2 : W3;
    float* WTo = WT + (size_t)z * DIMC * DIMC;
    int k0 = blockIdx.x * 32, n0 = blockIdx.y * 32;
    int tx = threadIdx.x, ty = threadIdx.y;   // 32 x 8
#pragma unroll
    for (int i = ty; i < 32; i += 8)
        tile[i][tx] = rna_tf32(W[(size_t)(k0 + i) * DIMC + n0 + tx]);
    __syncthreads();
#pragma unroll
    for (int i = ty; i < 32; i += 8)
        WTo[(size_t)(n0 + i) * DIMC + k0 + tx] = tile[tx][i];
}

// ---------------------------------------------------------------------------
// attention: one warp per (b,t,h); lane = RoPE pair (lane, lane+32).
__global__ __launch_bounds__(256) void attn_kernel(
    const float* __restrict__ q, const float* __restrict__ offr,
    const float* __restrict__ kall, const float* __restrict__ vall,
    float* __restrict__ out) {
    int warp = (blockIdx.x * blockDim.x + threadIdx.x) >> 5;
    int lane = threadIdx.x & 31;
    int h = warp % HH;
    int t = (warp / HH) % TT;
    int b = warp / (HH * TT);
    if (b >= BB) return;

    const float LOG1E4 = 9.210340371976184f;
    float inv_freq = __expf(-(float)lane * (LOG1E4 / 32.0f));

    size_t qbase = ((size_t)(b * TT + t) * DIMC) + h * DHH + lane;
    float q1 = q[qbase], q2 = q[qbase + 32];
    float sq, cq;
    sincosf((float)t * inv_freq, &sq, &cq);
    float q1r = q1 * cq - q2 * sq;
    float q2r = q1 * sq + q2 * cq;

    float refp = (float)t * (1.0f / (float)(TT - 1));

    float p[LL * KKS];
    float vs1[LL * KKS], vs2[LL * KKS];

    const int TsA[3]     = {2048, 1024, 512};
    const int rowbase[3] = {0, 4096, 6144};
    int offb = ((b * TT + t) * HH + h) * (LL * KKS);

    float idxA[LL * KKS], w1A[LL * KKS];
    int   o0A[LL * KKS], o1A[LL * KKS];
#pragma unroll
    for (int l = 0; l < LL; l++) {
        int Ts = TsA[l];
        float Tm1 = (float)(Ts - 1);
        int lvb = (rowbase[l] + b * Ts) * DIMC + h * DHH + lane;
#pragma unroll
        for (int k = 0; k < KKS; k++) {
            int li = l * KKS + k;
            float ofv = tanhf(offr[offb + li]) * 0.25f;
            float s = fminf(fmaxf(refp + ofv, 0.f), 1.f);
            float idx = fminf(s * Tm1, Tm1 - 1e-6f);
            int i0 = (int)idx;
            int i1 = min(i0 + 1, Ts - 1);
            idxA[li] = idx;
            w1A[li]  = idx - (float)i0;
            o0A[li]  = lvb + i0 * DIMC;
            o1A[li]  = lvb + i1 * DIMC;
        }
    }

#pragma unroll
    for (int li = 0; li < LL * KKS; li++) {
        float w1 = w1A[li], w0 = 1.f - w1;
        const float* k0p = kall + o0A[li];
        const float* k1p = kall + o1A[li];
        const float* v0p = vall + o0A[li];
        const float* v1p = vall + o1A[li];
        float k0a = k0p[0],  k1a = k1p[0];
        float k0b = k0p[32], k1b = k1p[32];
        float v0a = v0p[0],  v1a = v1p[0];
        float v0b = v0p[32], v1b = v1p[32];

        float ks1 = w0 * k0a + w1 * k1a;
        float ks2 = w0 * k0b + w1 * k1b;
        vs1[li]   = w0 * v0a + w1 * v1a;
        vs2[li]   = w0 * v0b + w1 * v1b;

        float si, co;
        sincosf(idxA[li] * inv_freq, &si, &co);
        float kr1 = ks1 * co - ks2 * si;
        float kr2 = ks1 * si + ks2 * co;
        p[li] = q1r * kr1 + q2r * kr2;
    }

#pragma unroll
    for (int d = 16; d > 0; d >>= 1) {
#pragma unroll
        for (int li = 0; li < LL * KKS; li++)
            p[li] += __shfl_xor_sync(0xffffffffu, p[li], d);
    }

    float m = p[0] * 0.125f;
#pragma unroll
    for (int i = 1; i < LL * KKS; i++) m = fmaxf(m, p[i] * 0.125f);
    float den = 0.f;
#pragma unroll
    for (int i = 0; i < LL * KKS; i++) {
        p[i] = __expf(p[i] * 0.125f - m);
        den += p[i];
    }
    float rden = 1.f / den;
    float o1 = 0.f, o2 = 0.f;
#pragma unroll
    for (int i = 0; i < LL * KKS; i++) {
        float a = p[i] * rden;
        o1 += a * vs1[i];
        o2 += a * vs2[i];
    }
    out[qbase]      = rna_tf32(o1);
    out[qbase + 32] = rna_tf32(o2);
}

// ---------------------------------------------------------------------------
extern "C" void kernel_launch(void* const* d_in, const int* in_sizes, int n_in,
                              void* d_out, int out_size) {
    const float* x    = (const float*)d_in[0];
    const float* Wq   = (const float*)d_in[2];
    const float* bq   = (const float*)d_in[3];
    const float* Wk   = (const float*)d_in[4];
    const float* bk   = (const float*)d_in[5];
    const float* Wv   = (const float*)d_in[6];
    const float* bv   = (const float*)d_in[7];
    const float* Woff = (const float*)d_in[8];
    const float* boff = (const float*)d_in[9];
    const float* Wo   = (const float*)d_in[10];
    const float* bo   = (const float*)d_in[11];
    float* out = (float*)d_out;

    float *xr, *qg, *offg, *kg, *vg, *aog, *wT;
    cudaGetSymbolAddress((void**)&xr,   g_xr);
    cudaGetSymbolAddress((void**)&qg,   g_q);
    cudaGetSymbolAddress((void**)&offg, g_off);
    cudaGetSymbolAddress((void**)&kg,   g_k);
    cudaGetSymbolAddress((void**)&vg,   g_v);
    cudaGetSymbolAddress((void**)&aog,  g_ao);
    cudaGetSymbolAddress((void**)&wT,   g_WqkvoT);

    cudaFuncSetAttribute(gemm_tf32, cudaFuncAttributeMaxDynamicSharedMemorySize,
                         GEMM_SMEM);

    // 0) tf32-round x; fused transpose+round of all 4 weights
    {
        int n4 = BB * TT * DIMC / 4;
        rna_copy<<<(n4 + 255) / 256, 256>>>((const float4*)x, (float4*)xr, n4);
        transpose_rna4<<<dim3(32, 32, 4), dim3(32, 8)>>>(Wq, Wk, Wv, Wo, wT);
    }

    // 1) offset projection in EXACT fp32 (index-sensitive; tf32 -> 15% error)
    {
        dim3 grid(2, (BB * TT) / 128);
        sgemm_bias<<<grid, 256>>>(BB * TT, HH * LL * KKS, DIMC, x, Woff, boff, offg);
    }

    // 2) fused Q/K/V level-0 projection: x @ [Wq|Wk|Wv] (N=3072)
    gemm_tf32<<<dim3(12, 32), 512, GEMM_SMEM>>>(
        xr, wT, bq, bk, bv, qg, kg, vg);

    // 3) K/V pyramid levels by row-downsampling level-0 K/V
    {
        int n1 = BB * 1024 * (DIMC / 4);
        int n2 = BB * 512  * (DIMC / 4);
        downsample_kernel<<<(n1 + 255) / 256, 256>>>(kg, kg + (size_t)4096 * DIMC, 1024);
        downsample_kernel<<<(n1 + 255) / 256, 256>>>(vg, vg + (size_t)4096 * DIMC, 1024);
        downsample_kernel<<<(n2 + 255) / 256, 256>>>(kg + (size_t)4096 * DIMC,
                                                     kg + (size_t)6144 * DIMC, 512);
        downsample_kernel<<<(n2 + 255) / 256, 256>>>(vg + (size_t)4096 * DIMC,
                                                     vg + (size_t)6144 * DIMC, 512);
    }

    // 4) deformable attention
    {
        int warps = BB * TT * HH;
        attn_kernel<<<warps / 8, 256>>>(qg, offg, kg, vg, aog);
    }

    // 5) output projection -> d_out  (Wo is segment 3 of wT)
    gemm_tf32<<<dim3(4, 32), 512, GEMM_SMEM>>>(
        aog, wT + (size_t)3 * DIMC * DIMC, bo, bo, bo, out, out, out);
}

// round 10
// speedup vs baseline: 1.3019x; 1.3019x over previous
#include <cuda_runtime.h>
#include <math.h>
#include <stdint.h>

// ---------------------------------------------------------------------------
// Problem constants (fixed by setup_inputs)
#define BB   2
#define TT   2048
#define DIMC 1024
#define HH   16
#define DHH  64
#define LL   3
#define KKS  4
#define TOTROWS 7168           // 4096 + 2048 + 1024 rows of K/V

// GEMM tiling: 128x128 CTA tile, BK=32, 3-stage cp.async, 8 warps (64x32 each),
// capped at 128 regs/thread so 2 CTAs co-reside per SM (independent barriers).
#define BM 128
#define BN 128
#define BK 32
#define NSTAGE 3
#define NT (DIMC / BK)          // 32 k-iterations
#define ROWF 36                 // smem row stride in floats (144B)
#define TILEF (BM * ROWF)       // 4608 floats per tile (A or B)
#define STAGEF (2 * TILEF)      // 9216 floats
#define GEMM_SMEM (NSTAGE * STAGEF * 4)   // 110592 bytes -> 2 CTAs/SM

// ---------------------------------------------------------------------------
// scratch (device globals; no allocation allowed)
__device__ float g_xr    [BB * TT * DIMC];           // tf32-rounded x
__device__ float g_q     [BB * TT * DIMC];
__device__ float g_off   [BB * TT * HH * LL * KKS];
__device__ float g_k     [TOTROWS * DIMC];
__device__ float g_v     [TOTROWS * DIMC];
__device__ float g_ao    [BB * TT * DIMC];
__device__ float g_WqkvoT[4 * DIMC * DIMC];          // [Wq;Wk;Wv;Wo] transposed [N,K]

// ---------------------------------------------------------------------------
__device__ __forceinline__ float rna_tf32(float x) {
    float r;
    asm("cvt.rna.tf32.f32 %0, %1;" : "=f"(r) : "f"(x));
    return r;
}
__device__ __forceinline__ uint32_t smem_u32(const void* p) {
    uint32_t a;
    asm("{ .reg .u64 t; cvta.to.shared.u64 t, %1; cvt.u32.u64 %0, t; }"
        : "=r"(a) : "l"(p));
    return a;
}
__device__ __forceinline__ void cp_async16(uint32_t dst, const void* src) {
    asm volatile("cp.async.cg.shared.global [%0], [%1], 16;"
                 :: "r"(dst), "l"(src) : "memory");
}
__device__ __forceinline__ void cp_commit() {
    asm volatile("cp.async.commit_group;" ::: "memory");
}
template <int N>
__device__ __forceinline__ void cp_wait() {
    asm volatile("cp.async.wait_group %0;" :: "n"(N) : "memory");
}
__device__ __forceinline__ void mma_tf32(float& d0, float& d1, float& d2, float& d3,
                                         uint32_t a0, uint32_t a1, uint32_t a2, uint32_t a3,
                                         uint32_t b0, uint32_t b1) {
    asm volatile(
        "mma.sync.aligned.m16n8k8.row.col.f32.tf32.tf32.f32 "
        "{%0,%1,%2,%3}, {%4,%5,%6,%7}, {%8,%9}, {%0,%1,%2,%3};"
        : "+f"(d0), "+f"(d1), "+f"(d2), "+f"(d3)
        : "r"(a0), "r"(a1), "r"(a2), "r"(a3), "r"(b0), "r"(b1));
}

// ---------------------------------------------------------------------------
// tf32 mma.sync GEMM, 128x128 tile, 8 warps (2x4, 64x32 warp tiles),
// segmented output routing (BN=128 -> 8 CTAs per 1024-col segment).
__global__ __launch_bounds__(256, 2) void gemm_tf32(
    const float* __restrict__ A, const float* __restrict__ BT,
    const float* __restrict__ b0, const float* __restrict__ b1,
    const float* __restrict__ b2,
    float* __restrict__ C0, float* __restrict__ C1, float* __restrict__ C2) {
    extern __shared__ float smem[];

    int tid  = threadIdx.x;
    int wid  = tid >> 5, lane = tid & 31;
    int gid  = lane >> 2, tg = lane & 3;
    int wm   = wid >> 2;          // 0..1 (64-row band)
    int wn   = wid & 3;           // 0..3 (32-col band)
    int m0   = blockIdx.y * BM;

    int seg  = blockIdx.x >> 3;
    int ncol = (blockIdx.x & 7) * BN;
    const float* bias = (seg == 0) ? b0 : (seg == 1) ? b1 : b2;
    float* C          = (seg == 0) ? C0 : (seg == 1) ? C1 : C2;

    uint32_t sbase = smem_u32(smem);

    const float* Abase = A  + (size_t)m0 * DIMC;
    const float* Bbase = BT + (size_t)blockIdx.x * BN * DIMC;

    float acc[4][4][4];
#pragma unroll
    for (int mi = 0; mi < 4; mi++)
#pragma unroll
        for (int ni = 0; ni < 4; ni++)
#pragma unroll
            for (int r = 0; r < 4; r++) acc[mi][ni][r] = 0.f;

    // per-stage async copy: A tile 4 chunks/thread, B tile 4 chunks/thread
#define ISSUE_STAGE(pt) do {                                                   \
        uint32_t sa_  = sbase + (((pt) % NSTAGE) * STAGEF) * 4;                \
        uint32_t sbB_ = sa_ + TILEF * 4;                                       \
        _Pragma("unroll")                                                      \
        for (int i_ = 0; i_ < 4; i_++) {                                       \
            int cid_ = i_ * 256 + tid;                                         \
            int r_ = cid_ >> 3, c_ = cid_ & 7;                                 \
            cp_async16(sa_ + (r_ * ROWF + c_ * 4) * 4,                         \
                       Abase + (size_t)r_ * DIMC + (pt) * BK + c_ * 4);        \
            cp_async16(sbB_ + (r_ * ROWF + c_ * 4) * 4,                        \
                       Bbase + (size_t)r_ * DIMC + (pt) * BK + c_ * 4);        \
        }                                                                      \
        cp_commit();                                                           \
    } while (0)

    ISSUE_STAGE(0);
    ISSUE_STAGE(1);

    for (int kt = 0; kt < NT; kt++) {
        if (kt + 2 < NT) cp_wait<1>(); else cp_wait<0>();
        __syncthreads();   // stage kt visible AND stage (kt+2)%3 free

        if (kt + 2 < NT) ISSUE_STAGE(kt + 2);

        const uint32_t* Au = (const uint32_t*)(smem + (kt % NSTAGE) * STAGEF);
        const uint32_t* Bu = Au + TILEF;

#pragma unroll
        for (int j = 0; j < 4; j++) {
            uint32_t af[4][4], bf[4][2];
            int kb = j * 8 + tg;
#pragma unroll
            for (int mi = 0; mi < 4; mi++) {
                int mrow = wm * 64 + mi * 16 + gid;
                af[mi][0] = Au[mrow * ROWF + kb];
                af[mi][1] = Au[(mrow + 8) * ROWF + kb];
                af[mi][2] = Au[mrow * ROWF + kb + 4];
                af[mi][3] = Au[(mrow + 8) * ROWF + kb + 4];
            }
#pragma unroll
            for (int ni = 0; ni < 4; ni++) {
                int nrow = wn * 32 + ni * 8 + gid;
                bf[ni][0] = Bu[nrow * ROWF + kb];
                bf[ni][1] = Bu[nrow * ROWF + kb + 4];
            }
#pragma unroll
            for (int mi = 0; mi < 4; mi++)
#pragma unroll
                for (int ni = 0; ni < 4; ni++)
                    mma_tf32(acc[mi][ni][0], acc[mi][ni][1],
                             acc[mi][ni][2], acc[mi][ni][3],
                             af[mi][0], af[mi][1], af[mi][2], af[mi][3],
                             bf[ni][0], bf[ni][1]);
        }
    }

#pragma unroll
    for (int mi = 0; mi < 4; mi++) {
        int r0 = m0 + wm * 64 + mi * 16 + gid;
#pragma unroll
        for (int ni = 0; ni < 4; ni++) {
            int c = ncol + wn * 32 + ni * 8 + tg * 2;
            float bx = bias[c], by = bias[c + 1];
            float2 o0 = make_float2(acc[mi][ni][0] + bx, acc[mi][ni][1] + by);
            float2 o1 = make_float2(acc[mi][ni][2] + bx, acc[mi][ni][3] + by);
            *(float2*)&C[(size_t)r0 * DIMC + c] = o0;
            *(float2*)&C[(size_t)(r0 + 8) * DIMC + c] = o1;
        }
    }
#undef ISSUE_STAGE
}

// ---------------------------------------------------------------------------
// fp32 SGEMM (exact) for the offset projection: C[M,N] = A@W + bias, N=192
__global__ __launch_bounds__(256) void sgemm_bias(
    int M, int N, int K,
    const float* __restrict__ A, const float* __restrict__ W,
    const float* __restrict__ bias, float* __restrict__ C) {
    __shared__ float As[8][128];
    __shared__ float Bs[8][128];

    int tid = threadIdx.x;
    int bm = blockIdx.y, bn = blockIdx.x;

    int aRow = tid >> 1;
    int aCol = (tid & 1) * 4;
    int bRow = tid >> 5;
    int bCol = (tid & 31) * 4;
    int wcol = bn * 128 + bCol;

    int tRow = (tid >> 4) * 8;
    int tCol = (tid & 15) * 8;

    const float* Ab = A + (size_t)(bm * 128 + aRow) * K + aCol;

    float acc[8][8];
#pragma unroll
    for (int i = 0; i < 8; i++)
#pragma unroll
        for (int j = 0; j < 8; j++) acc[i][j] = 0.f;

    for (int k0 = 0; k0 < K; k0 += 8) {
        float4 av = *(const float4*)(Ab + k0);
        As[aCol + 0][aRow] = av.x;
        As[aCol + 1][aRow] = av.y;
        As[aCol + 2][aRow] = av.z;
        As[aCol + 3][aRow] = av.w;
        float4 wv = make_float4(0.f, 0.f, 0.f, 0.f);
        if (wcol < N)
            wv = *(const float4*)(W + (size_t)(k0 + bRow) * N + wcol);
        *(float4*)&Bs[bRow][bCol] = wv;
        __syncthreads();
#pragma unroll
        for (int kk = 0; kk < 8; kk++) {
            float4 a0 = *(const float4*)&As[kk][tRow];
            float4 a1 = *(const float4*)&As[kk][tRow + 4];
            float4 b0 = *(const float4*)&Bs[kk][tCol];
            float4 b1 = *(const float4*)&Bs[kk][tCol + 4];
            float av8[8] = {a0.x, a0.y, a0.z, a0.w, a1.x, a1.y, a1.z, a1.w};
            float bv8[8] = {b0.x, b0.y, b0.z, b0.w, b1.x, b1.y, b1.z, b1.w};
#pragma unroll
            for (int i = 0; i < 8; i++)
#pragma unroll
                for (int j = 0; j < 8; j++) acc[i][j] += av8[i] * bv8[j];
        }
        __syncthreads();
    }

#pragma unroll
    for (int i = 0; i < 8; i++) {
        size_t row = (size_t)(bm * 128 + tRow + i);
#pragma unroll
        for (int j = 0; j < 8; j += 4) {
            int col = bn * 128 + tCol + j;
            if (col < N) {
                float4 o;
                o.x = acc[i][j + 0] + bias[col + 0];
                o.y = acc[i][j + 1] + bias[col + 1];
                o.z = acc[i][j + 2] + bias[col + 2];
                o.w = acc[i][j + 3] + bias[col + 3];
                *(float4*)&C[row * N + col] = o;
            }
        }
    }
}

// ---------------------------------------------------------------------------
__global__ void rna_copy(const float4* __restrict__ in, float4* __restrict__ out, int n4) {
    int i = blockIdx.x * blockDim.x + threadIdx.x;
    if (i >= n4) return;
    float4 v = in[i];
    v.x = rna_tf32(v.x); v.y = rna_tf32(v.y);
    v.z = rna_tf32(v.z); v.w = rna_tf32(v.w);
    out[i] = v;
}

// row-pair average on K/V (downsample commutes with linear projection)
__global__ void downsample_kernel(const float* __restrict__ in,
                                  float* __restrict__ out, int Tout) {
    int i = blockIdx.x * blockDim.x + threadIdx.x;
    int c4 = i % (DIMC / 4);
    int t  = (i / (DIMC / 4)) % Tout;
    int b  = i / (Tout * (DIMC / 4));
    if (b >= BB) return;
    const float4* in4 = (const float4*)in;
    float4 a = in4[((size_t)b * 2 * Tout + 2 * t)     * (DIMC / 4) + c4];
    float4 c = in4[((size_t)b * 2 * Tout + 2 * t + 1) * (DIMC / 4) + c4];
    float4 r;
    r.x = 0.5f * (a.x + c.x);
    r.y = 0.5f * (a.y + c.y);
    r.z = 0.5f * (a.z + c.z);
    r.w = 0.5f * (a.w + c.w);
    ((float4*)out)[i] = r;
}

// fused transpose + tf32 round for 4 weights: WT[z][n][k] = rna(W_z[k][n])
__global__ void transpose_rna4(const float* __restrict__ W0, const float* __restrict__ W1,
                               const float* __restrict__ W2, const float* __restrict__ W3,
                               float* __restrict__ WT) {
    __shared__ float tile[32][33];
    int z  = blockIdx.z;
    const float* W = (z == 0) ? W0 : (z == 1) ? W1 : (z == 2) ? W2 : W3;
    float* WTo = WT + (size_t)z * DIMC * DIMC;
    int k0 = blockIdx.x * 32, n0 = blockIdx.y * 32;
    int tx = threadIdx.x, ty = threadIdx.y;   // 32 x 8
#pragma unroll
    for (int i = ty; i < 32; i += 8)
        tile[i][tx] = rna_tf32(W[(size_t)(k0 + i) * DIMC + n0 + tx]);
    __syncthreads();
#pragma unroll
    for (int i = ty; i < 32; i += 8)
        WTo[(size_t)(n0 + i) * DIMC + k0 + tx] = tile[tx][i];
}

// ---------------------------------------------------------------------------
// attention: one warp per (b,t,h); lane = RoPE pair (lane, lane+32).
__global__ __launch_bounds__(256) void attn_kernel(
    const float* __restrict__ q, const float* __restrict__ offr,
    const float* __restrict__ kall, const float* __restrict__ vall,
    float* __restrict__ out) {
    int warp = (blockIdx.x * blockDim.x + threadIdx.x) >> 5;
    int lane = threadIdx.x & 31;
    int h = warp % HH;
    int t = (warp / HH) % TT;
    int b = warp / (HH * TT);
    if (b >= BB) return;

    const float LOG1E4 = 9.210340371976184f;
    float inv_freq = __expf(-(float)lane * (LOG1E4 / 32.0f));

    size_t qbase = ((size_t)(b * TT + t) * DIMC) + h * DHH + lane;
    float q1 = q[qbase], q2 = q[qbase + 32];
    float sq, cq;
    sincosf((float)t * inv_freq, &sq, &cq);
    float q1r = q1 * cq - q2 * sq;
    float q2r = q1 * sq + q2 * cq;

    float refp = (float)t * (1.0f / (float)(TT - 1));

    float p[LL * KKS];
    float vs1[LL * KKS], vs2[LL * KKS];

    const int TsA[3]     = {2048, 1024, 512};
    const int rowbase[3] = {0, 4096, 6144};
    int offb = ((b * TT + t) * HH + h) * (LL * KKS);

    float idxA[LL * KKS], w1A[LL * KKS];
    int   o0A[LL * KKS], o1A[LL * KKS];
#pragma unroll
    for (int l = 0; l < LL; l++) {
        int Ts = TsA[l];
        float Tm1 = (float)(Ts - 1);
        int lvb = (rowbase[l] + b * Ts) * DIMC + h * DHH + lane;
#pragma unroll
        for (int k = 0; k < KKS; k++) {
            int li = l * KKS + k;
            float ofv = tanhf(offr[offb + li]) * 0.25f;
            float s = fminf(fmaxf(refp + ofv, 0.f), 1.f);
            float idx = fminf(s * Tm1, Tm1 - 1e-6f);
            int i0 = (int)idx;
            int i1 = min(i0 + 1, Ts - 1);
            idxA[li] = idx;
            w1A[li]  = idx - (float)i0;
            o0A[li]  = lvb + i0 * DIMC;
            o1A[li]  = lvb + i1 * DIMC;
        }
    }

#pragma unroll
    for (int li = 0; li < LL * KKS; li++) {
        float w1 = w1A[li], w0 = 1.f - w1;
        const float* k0p = kall + o0A[li];
        const float* k1p = kall + o1A[li];
        const float* v0p = vall + o0A[li];
        const float* v1p = vall + o1A[li];
        float k0a = k0p[0],  k1a = k1p[0];
        float k0b = k0p[32], k1b = k1p[32];
        float v0a = v0p[0],  v1a = v1p[0];
        float v0b = v0p[32], v1b = v1p[32];

        float ks1 = w0 * k0a + w1 * k1a;
        float ks2 = w0 * k0b + w1 * k1b;
        vs1[li]   = w0 * v0a + w1 * v1a;
        vs2[li]   = w0 * v0b + w1 * v1b;

        float si, co;
        sincosf(idxA[li] * inv_freq, &si, &co);
        float kr1 = ks1 * co - ks2 * si;
        float kr2 = ks1 * si + ks2 * co;
        p[li] = q1r * kr1 + q2r * kr2;
    }

#pragma unroll
    for (int d = 16; d > 0; d >>= 1) {
#pragma unroll
        for (int li = 0; li < LL * KKS; li++)
            p[li] += __shfl_xor_sync(0xffffffffu, p[li], d);
    }

    float m = p[0] * 0.125f;
#pragma unroll
    for (int i = 1; i < LL * KKS; i++) m = fmaxf(m, p[i] * 0.125f);
    float den = 0.f;
#pragma unroll
    for (int i = 0; i < LL * KKS; i++) {
        p[i] = __expf(p[i] * 0.125f - m);
        den += p[i];
    }
    float rden = 1.f / den;
    float o1 = 0.f, o2 = 0.f;
#pragma unroll
    for (int i = 0; i < LL * KKS; i++) {
        float a = p[i] * rden;
        o1 += a * vs1[i];
        o2 += a * vs2[i];
    }
    out[qbase]      = rna_tf32(o1);
    out[qbase + 32] = rna_tf32(o2);
}

// ---------------------------------------------------------------------------
extern "C" void kernel_launch(void* const* d_in, const int* in_sizes, int n_in,
                              void* d_out, int out_size) {
    const float* x    = (const float*)d_in[0];
    const float* Wq   = (const float*)d_in[2];
    const float* bq   = (const float*)d_in[3];
    const float* Wk   = (const float*)d_in[4];
    const float* bk   = (const float*)d_in[5];
    const float* Wv   = (const float*)d_in[6];
    const float* bv   = (const float*)d_in[7];
    const float* Woff = (const float*)d_in[8];
    const float* boff = (const float*)d_in[9];
    const float* Wo   = (const float*)d_in[10];
    const float* bo   = (const float*)d_in[11];
    float* out = (float*)d_out;

    float *xr, *qg, *offg, *kg, *vg, *aog, *wT;
    cudaGetSymbolAddress((void**)&xr,   g_xr);
    cudaGetSymbolAddress((void**)&qg,   g_q);
    cudaGetSymbolAddress((void**)&offg, g_off);
    cudaGetSymbolAddress((void**)&kg,   g_k);
    cudaGetSymbolAddress((void**)&vg,   g_v);
    cudaGetSymbolAddress((void**)&aog,  g_ao);
    cudaGetSymbolAddress((void**)&wT,   g_WqkvoT);

    cudaFuncSetAttribute(gemm_tf32, cudaFuncAttributeMaxDynamicSharedMemorySize,
                         GEMM_SMEM);

    // side stream + events for capture-legal fork/join (created once; resources
    // only, no device memory; work is identical on every call)
    static cudaStream_t s_side = nullptr;
    static cudaEvent_t e_fork = nullptr, e_join = nullptr;
    if (s_side == nullptr) {
        cudaStreamCreateWithFlags(&s_side, cudaStreamNonBlocking);
        cudaEventCreateWithFlags(&e_fork, cudaEventDisableTiming);
        cudaEventCreateWithFlags(&e_join, cudaEventDisableTiming);
    }

    // fork: offset projection (exact fp32, depends only on x, feeds only attn)
    // runs concurrently with the tf32 pipeline below.
    cudaEventRecord(e_fork, 0);
    cudaStreamWaitEvent(s_side, e_fork, 0);
    {
        dim3 grid(2, (BB * TT) / 128);
        sgemm_bias<<<grid, 256, 0, s_side>>>(BB * TT, HH * LL * KKS, DIMC,
                                             x, Woff, boff, offg);
        cudaEventRecord(e_join, s_side);
    }

    // main stream: tf32-round x; transpose+round weights
    {
        int n4 = BB * TT * DIMC / 4;
        rna_copy<<<(n4 + 255) / 256, 256>>>((const float4*)x, (float4*)xr, n4);
        transpose_rna4<<<dim3(32, 32, 4), dim3(32, 8)>>>(Wq, Wk, Wv, Wo, wT);
    }

    // fused Q/K/V level-0 projection: x @ [Wq|Wk|Wv] (N=3072)
    gemm_tf32<<<dim3(24, 32), 256, GEMM_SMEM>>>(
        xr, wT, bq, bk, bv, qg, kg, vg);

    // K/V pyramid levels by row-downsampling level-0 K/V
    {
        int n1 = BB * 1024 * (DIMC / 4);
        int n2 = BB * 512  * (DIMC / 4);
        downsample_kernel<<<(n1 + 255) / 256, 256>>>(kg, kg + (size_t)4096 * DIMC, 1024);
        downsample_kernel<<<(n1 + 255) / 256, 256>>>(vg, vg + (size_t)4096 * DIMC, 1024);
        downsample_kernel<<<(n2 + 255) / 256, 256>>>(kg + (size_t)4096 * DIMC,
                                                     kg + (size_t)6144 * DIMC, 512);
        downsample_kernel<<<(n2 + 255) / 256, 256>>>(vg + (size_t)4096 * DIMC,
                                                     vg + (size_t)6144 * DIMC, 512);
    }

    // join: attention needs the offsets from the side stream
    cudaStreamWaitEvent(0, e_join, 0);

    // deformable attention
    {
        int warps = BB * TT * HH;
        attn_kernel<<<warps / 8, 256>>>(qg, offg, kg, vg, aog);
    }

    // output projection -> d_out  (Wo is segment 3 of wT)
    gemm_tf32<<<dim3(8, 32), 256, GEMM_SMEM>>>(
        aog, wT + (size_t)3 * DIMC * DIMC, bo, bo, bo, out, out, out);
}

// round 11
// speedup vs baseline: 1.3560x; 1.0416x over previous
#include <cuda_runtime.h>
#include <math.h>
#include <stdint.h>

// ---------------------------------------------------------------------------
// Problem constants (fixed by setup_inputs)
#define BB   2
#define TT   2048
#define DIMC 1024
#define HH   16
#define DHH  64
#define LL   3
#define KKS  4
#define TOTROWS 7168           // 4096 + 2048 + 1024 rows of K/V

// GEMM tiling: 128x128 CTA tile, BK=32, 3-stage cp.async, 8 warps (64x32 each),
// <=128 regs/thread so 2 CTAs co-reside per SM. Fragments via ldmatrix.
#define BM 128
#define BN 128
#define BK 32
#define NSTAGE 3
#define NT (DIMC / BK)          // 32 k-iterations
#define ROWF 36                 // smem row stride in floats (144B)
#define TILEF (BM * ROWF)       // 4608 floats per tile (A or B)
#define STAGEF (2 * TILEF)      // 9216 floats
#define GEMM_SMEM (NSTAGE * STAGEF * 4)   // 110592 bytes -> 2 CTAs/SM

// ---------------------------------------------------------------------------
// scratch (device globals; no allocation allowed)
__device__ float g_xr    [BB * TT * DIMC];           // tf32-rounded x
__device__ float g_q     [BB * TT * DIMC];
__device__ float g_off   [BB * TT * HH * LL * KKS];
__device__ float g_k     [TOTROWS * DIMC];
__device__ float g_v     [TOTROWS * DIMC];
__device__ float g_ao    [BB * TT * DIMC];
__device__ float g_WqkvoT[4 * DIMC * DIMC];          // [Wq;Wk;Wv;Wo] transposed [N,K]

// ---------------------------------------------------------------------------
__device__ __forceinline__ float rna_tf32(float x) {
    float r;
    asm("cvt.rna.tf32.f32 %0, %1;" : "=f"(r) : "f"(x));
    return r;
}
__device__ __forceinline__ uint32_t smem_u32(const void* p) {
    uint32_t a;
    asm("{ .reg .u64 t; cvta.to.shared.u64 t, %1; cvt.u32.u64 %0, t; }"
        : "=r"(a) : "l"(p));
    return a;
}
__device__ __forceinline__ void cp_async16(uint32_t dst, const void* src) {
    asm volatile("cp.async.cg.shared.global [%0], [%1], 16;"
                 :: "r"(dst), "l"(src) : "memory");
}
__device__ __forceinline__ void cp_commit() {
    asm volatile("cp.async.commit_group;" ::: "memory");
}
template <int N>
__device__ __forceinline__ void cp_wait() {
    asm volatile("cp.async.wait_group %0;" :: "n"(N) : "memory");
}
__device__ __forceinline__ void ldsm_x4(uint32_t& r0, uint32_t& r1,
                                        uint32_t& r2, uint32_t& r3, uint32_t addr) {
    asm volatile("ldmatrix.sync.aligned.m8n8.x4.shared.b16 {%0,%1,%2,%3}, [%4];"
                 : "=r"(r0), "=r"(r1), "=r"(r2), "=r"(r3) : "r"(addr));
}
__device__ __forceinline__ void mma_tf32(float& d0, float& d1, float& d2, float& d3,
                                         uint32_t a0, uint32_t a1, uint32_t a2, uint32_t a3,
                                         uint32_t b0, uint32_t b1) {
    asm volatile(
        "mma.sync.aligned.m16n8k8.row.col.f32.tf32.tf32.f32 "
        "{%0,%1,%2,%3}, {%4,%5,%6,%7}, {%8,%9}, {%0,%1,%2,%3};"
        : "+f"(d0), "+f"(d1), "+f"(d2), "+f"(d3)
        : "r"(a0), "r"(a1), "r"(a2), "r"(a3), "r"(b0), "r"(b1));
}

// ---------------------------------------------------------------------------
// tf32 mma.sync GEMM, 128x128 tile, 8 warps (2x4, 64x32 warp tiles),
// ldmatrix fragment loads, segmented output routing (8 CTAs / 1024-col segment).
__global__ __launch_bounds__(256, 2) void gemm_tf32(
    const float* __restrict__ A, const float* __restrict__ BT,
    const float* __restrict__ b0, const float* __restrict__ b1,
    const float* __restrict__ b2,
    float* __restrict__ C0, float* __restrict__ C1, float* __restrict__ C2) {
    extern __shared__ float smem[];

    int tid  = threadIdx.x;
    int wid  = tid >> 5, lane = tid & 31;
    int gid  = lane >> 2, tg = lane & 3;
    int wm   = wid >> 2;          // 0..1 (64-row band)
    int wn   = wid & 3;           // 0..3 (32-col band)
    int m0   = blockIdx.y * BM;

    int seg  = blockIdx.x >> 3;
    int ncol = (blockIdx.x & 7) * BN;
    const float* bias = (seg == 0) ? b0 : (seg == 1) ? b1 : b2;
    float* C          = (seg == 0) ? C0 : (seg == 1) ? C1 : C2;

    uint32_t sbase = smem_u32(smem);

    const float* Abase = A  + (size_t)m0 * DIMC;
    const float* Bbase = BT + (size_t)blockIdx.x * BN * DIMC;

    // ldmatrix lane address offsets (bytes, within a stage's A / B tile).
    // x4 matrices: m0=(rows+0..7, k0..3) m1=(rows+8..15, k0..3)
    //              m2=(rows+0..7, k4..7) m3=(rows+8..15, k4..7)
    // lane i serves matrix i>>3, row i&7.
    int lrow = lane & 7;
    int lm8  = (lane >> 3) & 1;   // +8 rows for m1/m3
    int lk4  = (lane >> 4) & 1;   // +4 k for m2/m3
    uint32_t a_off[4];
#pragma unroll
    for (int mi = 0; mi < 4; mi++) {
        int row = wm * 64 + mi * 16 + lm8 * 8 + lrow;
        a_off[mi] = (uint32_t)((row * ROWF + lk4 * 4) * 4);
    }
    // B x4 matrices for an ni-pair p: m0=(n+0..7,k0..3) m1=(n+0..7,k4..7)
    //                                 m2=(n+8..15,k0..3) m3=(n+8..15,k4..7)
    uint32_t bt_off[2];
#pragma unroll
    for (int p = 0; p < 2; p++) {
        int n = wn * 32 + p * 16 + lk4 * 8 + lrow;
        bt_off[p] = (uint32_t)((n * ROWF + lm8 * 4) * 4);
    }

    float acc[4][4][4];
#pragma unroll
    for (int mi = 0; mi < 4; mi++)
#pragma unroll
        for (int ni = 0; ni < 4; ni++)
#pragma unroll
            for (int r = 0; r < 4; r++) acc[mi][ni][r] = 0.f;

#define ISSUE_STAGE(pt) do {                                                   \
        uint32_t sa_  = sbase + (((pt) % NSTAGE) * STAGEF) * 4;                \
        uint32_t sbB_ = sa_ + TILEF * 4;                                       \
        _Pragma("unroll")                                                      \
        for (int i_ = 0; i_ < 4; i_++) {                                       \
            int cid_ = i_ * 256 + tid;                                         \
            int r_ = cid_ >> 3, c_ = cid_ & 7;                                 \
            cp_async16(sa_ + (r_ * ROWF + c_ * 4) * 4,                         \
                       Abase + (size_t)r_ * DIMC + (pt) * BK + c_ * 4);        \
            cp_async16(sbB_ + (r_ * ROWF + c_ * 4) * 4,                        \
                       Bbase + (size_t)r_ * DIMC + (pt) * BK + c_ * 4);        \
        }                                                                      \
        cp_commit();                                                           \
    } while (0)

    ISSUE_STAGE(0);
    ISSUE_STAGE(1);

    for (int kt = 0; kt < NT; kt++) {
        if (kt + 2 < NT) cp_wait<1>(); else cp_wait<0>();
        __syncthreads();   // stage kt visible AND stage (kt+2)%3 free

        if (kt + 2 < NT) ISSUE_STAGE(kt + 2);

        uint32_t abase = sbase + ((kt % NSTAGE) * STAGEF) * 4;
        uint32_t bbase = abase + TILEF * 4;

#pragma unroll
        for (int j = 0; j < 4; j++) {
            uint32_t af[4][4], bf[4][2];
            uint32_t jb = (uint32_t)(j * 32);     // j*8 k-values * 4B
#pragma unroll
            for (int mi = 0; mi < 4; mi++)
                ldsm_x4(af[mi][0], af[mi][1], af[mi][2], af[mi][3],
                        abase + a_off[mi] + jb);
#pragma unroll
            for (int p = 0; p < 2; p++)
                ldsm_x4(bf[2 * p][0], bf[2 * p][1], bf[2 * p + 1][0],
                        bf[2 * p + 1][1], bbase + bt_off[p] + jb);
#pragma unroll
            for (int mi = 0; mi < 4; mi++)
#pragma unroll
                for (int ni = 0; ni < 4; ni++)
                    mma_tf32(acc[mi][ni][0], acc[mi][ni][1],
                             acc[mi][ni][2], acc[mi][ni][3],
                             af[mi][0], af[mi][1], af[mi][2], af[mi][3],
                             bf[ni][0], bf[ni][1]);
        }
    }

#pragma unroll
    for (int mi = 0; mi < 4; mi++) {
        int r0 = m0 + wm * 64 + mi * 16 + gid;
#pragma unroll
        for (int ni = 0; ni < 4; ni++) {
            int c = ncol + wn * 32 + ni * 8 + tg * 2;
            float bx = bias[c], by = bias[c + 1];
            float2 o0 = make_float2(acc[mi][ni][0] + bx, acc[mi][ni][1] + by);
            float2 o1 = make_float2(acc[mi][ni][2] + bx, acc[mi][ni][3] + by);
            *(float2*)&C[(size_t)r0 * DIMC + c] = o0;
            *(float2*)&C[(size_t)(r0 + 8) * DIMC + c] = o1;
        }
    }
#undef ISSUE_STAGE
}

// ---------------------------------------------------------------------------
// fp32 SGEMM (exact) for the offset projection: C[M,N] = A@W + bias, N=192
__global__ __launch_bounds__(256) void sgemm_bias(
    int M, int N, int K,
    const float* __restrict__ A, const float* __restrict__ W,
    const float* __restrict__ bias, float* __restrict__ C) {
    __shared__ float As[8][128];
    __shared__ float Bs[8][128];

    int tid = threadIdx.x;
    int bm = blockIdx.y, bn = blockIdx.x;

    int aRow = tid >> 1;
    int aCol = (tid & 1) * 4;
    int bRow = tid >> 5;
    int bCol = (tid & 31) * 4;
    int wcol = bn * 128 + bCol;

    int tRow = (tid >> 4) * 8;
    int tCol = (tid & 15) * 8;

    const float* Ab = A + (size_t)(bm * 128 + aRow) * K + aCol;

    float acc[8][8];
#pragma unroll
    for (int i = 0; i < 8; i++)
#pragma unroll
        for (int j = 0; j < 8; j++) acc[i][j] = 0.f;

    for (int k0 = 0; k0 < K; k0 += 8) {
        float4 av = *(const float4*)(Ab + k0);
        As[aCol + 0][aRow] = av.x;
        As[aCol + 1][aRow] = av.y;
        As[aCol + 2][aRow] = av.z;
        As[aCol + 3][aRow] = av.w;
        float4 wv = make_float4(0.f, 0.f, 0.f, 0.f);
        if (wcol < N)
            wv = *(const float4*)(W + (size_t)(k0 + bRow) * N + wcol);
        *(float4*)&Bs[bRow][bCol] = wv;
        __syncthreads();
#pragma unroll
        for (int kk = 0; kk < 8; kk++) {
            float4 a0 = *(const float4*)&As[kk][tRow];
            float4 a1 = *(const float4*)&As[kk][tRow + 4];
            float4 b0 = *(const float4*)&Bs[kk][tCol];
            float4 b1 = *(const float4*)&Bs[kk][tCol + 4];
            float av8[8] = {a0.x, a0.y, a0.z, a0.w, a1.x, a1.y, a1.z, a1.w};
            float bv8[8] = {b0.x, b0.y, b0.z, b0.w, b1.x, b1.y, b1.z, b1.w};
#pragma unroll
            for (int i = 0; i < 8; i++)
#pragma unroll
                for (int j = 0; j < 8; j++) acc[i][j] += av8[i] * bv8[j];
        }
        __syncthreads();
    }

#pragma unroll
    for (int i = 0; i < 8; i++) {
        size_t row = (size_t)(bm * 128 + tRow + i);
#pragma unroll
        for (int j = 0; j < 8; j += 4) {
            int col = bn * 128 + tCol + j;
            if (col < N) {
                float4 o;
                o.x = acc[i][j + 0] + bias[col + 0];
                o.y = acc[i][j + 1] + bias[col + 1];
                o.z = acc[i][j + 2] + bias[col + 2];
                o.w = acc[i][j + 3] + bias[col + 3];
                *(float4*)&C[row * N + col] = o;
            }
        }
    }
}

// ---------------------------------------------------------------------------
__global__ void rna_copy(const float4* __restrict__ in, float4* __restrict__ out, int n4) {
    int i = blockIdx.x * blockDim.x + threadIdx.x;
    if (i >= n4) return;
    float4 v = in[i];
    v.x = rna_tf32(v.x); v.y = rna_tf32(v.y);
    v.z = rna_tf32(v.z); v.w = rna_tf32(v.w);
    out[i] = v;
}

// row-pair average on K/V (downsample commutes with linear projection)
__global__ void downsample_kernel(const float* __restrict__ in,
                                  float* __restrict__ out, int Tout) {
    int i = blockIdx.x * blockDim.x + threadIdx.x;
    int c4 = i % (DIMC / 4);
    int t  = (i / (DIMC / 4)) % Tout;
    int b  = i / (Tout * (DIMC / 4));
    if (b >= BB) return;
    const float4* in4 = (const float4*)in;
    float4 a = in4[((size_t)b * 2 * Tout + 2 * t)     * (DIMC / 4) + c4];
    float4 c = in4[((size_t)b * 2 * Tout + 2 * t + 1) * (DIMC / 4) + c4];
    float4 r;
    r.x = 0.5f * (a.x + c.x);
    r.y = 0.5f * (a.y + c.y);
    r.z = 0.5f * (a.z + c.z);
    r.w = 0.5f * (a.w + c.w);
    ((float4*)out)[i] = r;
}

// fused transpose + tf32 round for 4 weights: WT[z][n][k] = rna(W_z[k][n])
__global__ void transpose_rna4(const float* __restrict__ W0, const float* __restrict__ W1,
                               const float* __restrict__ W2, const float* __restrict__ W3,
                               float* __restrict__ WT) {
    __shared__ float tile[32][33];
    int z  = blockIdx.z;
    const float* W = (z == 0) ? W0 : (z == 1) ? W1 : (z == 2) ? W2 : W3;
    float* WTo = WT + (size_t)z * DIMC * DIMC;
    int k0 = blockIdx.x * 32, n0 = blockIdx.y * 32;
    int tx = threadIdx.x, ty = threadIdx.y;   // 32 x 8
#pragma unroll
    for (int i = ty; i < 32; i += 8)
        tile[i][tx] = rna_tf32(W[(size_t)(k0 + i) * DIMC + n0 + tx]);
    __syncthreads();
#pragma unroll
    for (int i = ty; i < 32; i += 8)
        WTo[(size_t)(n0 + i) * DIMC + k0 + tx] = tile[tx][i];
}

// ---------------------------------------------------------------------------
// attention: one warp per (b,t,h); lane = RoPE pair (lane, lane+32).
__global__ __launch_bounds__(256) void attn_kernel(
    const float* __restrict__ q, const float* __restrict__ offr,
    const float* __restrict__ kall, const float* __restrict__ vall,
    float* __restrict__ out) {
    int warp = (blockIdx.x * blockDim.x + threadIdx.x) >> 5;
    int lane = threadIdx.x & 31;
    int h = warp % HH;
    int t = (warp / HH) % TT;
    int b = warp / (HH * TT);
    if (b >= BB) return;

    const float LOG1E4 = 9.210340371976184f;
    float inv_freq = __expf(-(float)lane * (LOG1E4 / 32.0f));

    size_t qbase = ((size_t)(b * TT + t) * DIMC) + h * DHH + lane;
    float q1 = q[qbase], q2 = q[qbase + 32];
    float sq, cq;
    sincosf((float)t * inv_freq, &sq, &cq);
    float q1r = q1 * cq - q2 * sq;
    float q2r = q1 * sq + q2 * cq;

    float refp = (float)t * (1.0f / (float)(TT - 1));

    float p[LL * KKS];
    float vs1[LL * KKS], vs2[LL * KKS];

    const int TsA[3]     = {2048, 1024, 512};
    const int rowbase[3] = {0, 4096, 6144};
    int offb = ((b * TT + t) * HH + h) * (LL * KKS);

    float idxA[LL * KKS], w1A[LL * KKS];
    int   o0A[LL * KKS], o1A[LL * KKS];
#pragma unroll
    for (int l = 0; l < LL; l++) {
        int Ts = TsA[l];
        float Tm1 = (float)(Ts - 1);
        int lvb = (rowbase[l] + b * Ts) * DIMC + h * DHH + lane;
#pragma unroll
        for (int k = 0; k < KKS; k++) {
            int li = l * KKS + k;
            float ofv = tanhf(offr[offb + li]) * 0.25f;
            float s = fminf(fmaxf(refp + ofv, 0.f), 1.f);
            float idx = fminf(s * Tm1, Tm1 - 1e-6f);
            int i0 = (int)idx;
            int i1 = min(i0 + 1, Ts - 1);
            idxA[li] = idx;
            w1A[li]  = idx - (float)i0;
            o0A[li]  = lvb + i0 * DIMC;
            o1A[li]  = lvb + i1 * DIMC;
        }
    }

#pragma unroll
    for (int li = 0; li < LL * KKS; li++) {
        float w1 = w1A[li], w0 = 1.f - w1;
        const float* k0p = kall + o0A[li];
        const float* k1p = kall + o1A[li];
        const float* v0p = vall + o0A[li];
        const float* v1p = vall + o1A[li];
        float k0a = k0p[0],  k1a = k1p[0];
        float k0b = k0p[32], k1b = k1p[32];
        float v0a = v0p[0],  v1a = v1p[0];
        float v0b = v0p[32], v1b = v1p[32];

        float ks1 = w0 * k0a + w1 * k1a;
        float ks2 = w0 * k0b + w1 * k1b;
        vs1[li]   = w0 * v0a + w1 * v1a;
        vs2[li]   = w0 * v0b + w1 * v1b;

        float si, co;
        sincosf(idxA[li] * inv_freq, &si, &co);
        float kr1 = ks1 * co - ks2 * si;
        float kr2 = ks1 * si + ks2 * co;
        p[li] = q1r * kr1 + q2r * kr2;
    }

#pragma unroll
    for (int d = 16; d > 0; d >>= 1) {
#pragma unroll
        for (int li = 0; li < LL * KKS; li++)
            p[li] += __shfl_xor_sync(0xffffffffu, p[li], d);
    }

    float m = p[0] * 0.125f;
#pragma unroll
    for (int i = 1; i < LL * KKS; i++) m = fmaxf(m, p[i] * 0.125f);
    float den = 0.f;
#pragma unroll
    for (int i = 0; i < LL * KKS; i++) {
        p[i] = __expf(p[i] * 0.125f - m);
        den += p[i];
    }
    float rden = 1.f / den;
    float o1 = 0.f, o2 = 0.f;
#pragma unroll
    for (int i = 0; i < LL * KKS; i++) {
        float a = p[i] * rden;
        o1 += a * vs1[i];
        o2 += a * vs2[i];
    }
    out[qbase]      = rna_tf32(o1);
    out[qbase + 32] = rna_tf32(o2);
}

// ---------------------------------------------------------------------------
extern "C" void kernel_launch(void* const* d_in, const int* in_sizes, int n_in,
                              void* d_out, int out_size) {
    const float* x    = (const float*)d_in[0];
    const float* Wq   = (const float*)d_in[2];
    const float* bq   = (const float*)d_in[3];
    const float* Wk   = (const float*)d_in[4];
    const float* bk   = (const float*)d_in[5];
    const float* Wv   = (const float*)d_in[6];
    const float* bv   = (const float*)d_in[7];
    const float* Woff = (const float*)d_in[8];
    const float* boff = (const float*)d_in[9];
    const float* Wo   = (const float*)d_in[10];
    const float* bo   = (const float*)d_in[11];
    float* out = (float*)d_out;

    float *xr, *qg, *offg, *kg, *vg, *aog, *wT;
    cudaGetSymbolAddress((void**)&xr,   g_xr);
    cudaGetSymbolAddress((void**)&qg,   g_q);
    cudaGetSymbolAddress((void**)&offg, g_off);
    cudaGetSymbolAddress((void**)&kg,   g_k);
    cudaGetSymbolAddress((void**)&vg,   g_v);
    cudaGetSymbolAddress((void**)&aog,  g_ao);
    cudaGetSymbolAddress((void**)&wT,   g_WqkvoT);

    cudaFuncSetAttribute(gemm_tf32, cudaFuncAttributeMaxDynamicSharedMemorySize,
                         GEMM_SMEM);

    // side stream + events for capture-legal fork/join (resources only)
    static cudaStream_t s_side = nullptr;
    static cudaEvent_t e_fork = nullptr, e_join = nullptr;
    if (s_side == nullptr) {
        cudaStreamCreateWithFlags(&s_side, cudaStreamNonBlocking);
        cudaEventCreateWithFlags(&e_fork, cudaEventDisableTiming);
        cudaEventCreateWithFlags(&e_join, cudaEventDisableTiming);
    }

    // fork: offset projection (exact fp32, depends only on x, feeds only attn)
    cudaEventRecord(e_fork, 0);
    cudaStreamWaitEvent(s_side, e_fork, 0);
    {
        dim3 grid(2, (BB * TT) / 128);
        sgemm_bias<<<grid, 256, 0, s_side>>>(BB * TT, HH * LL * KKS, DIMC,
                                             x, Woff, boff, offg);
        cudaEventRecord(e_join, s_side);
    }

    // main stream: tf32-round x; transpose+round weights
    {
        int n4 = BB * TT * DIMC / 4;
        rna_copy<<<(n4 + 255) / 256, 256>>>((const float4*)x, (float4*)xr, n4);
        transpose_rna4<<<dim3(32, 32, 4), dim3(32, 8)>>>(Wq, Wk, Wv, Wo, wT);
    }

    // fused Q/K/V level-0 projection: x @ [Wq|Wk|Wv] (N=3072)
    gemm_tf32<<<dim3(24, 32), 256, GEMM_SMEM>>>(
        xr, wT, bq, bk, bv, qg, kg, vg);

    // K/V pyramid levels by row-downsampling level-0 K/V
    {
        int n1 = BB * 1024 * (DIMC / 4);
        int n2 = BB * 512  * (DIMC / 4);
        downsample_kernel<<<(n1 + 255) / 256, 256>>>(kg, kg + (size_t)4096 * DIMC, 1024);
        downsample_kernel<<<(n1 + 255) / 256, 256>>>(vg, vg + (size_t)4096 * DIMC, 1024);
        downsample_kernel<<<(n2 + 255) / 256, 256>>>(kg + (size_t)4096 * DIMC,
                                                     kg + (size_t)6144 * DIMC, 512);
        downsample_kernel<<<(n2 + 255) / 256, 256>>>(vg + (size_t)4096 * DIMC,
                                                     vg + (size_t)6144 * DIMC, 512);
    }

    // join: attention needs the offsets from the side stream
    cudaStreamWaitEvent(0, e_join, 0);

    // deformable attention
    {
        int warps = BB * TT * HH;
        attn_kernel<<<warps / 8, 256>>>(qg, offg, kg, vg, aog);
    }

    // output projection -> d_out  (Wo is segment 3 of wT)
    gemm_tf32<<<dim3(8, 32), 256, GEMM_SMEM>>>(
        aog, wT + (size_t)3 * DIMC * DIMC, bo, bo, bo, out, out, out);
}

// round 12
// speedup vs baseline: 1.3583x; 1.0017x over previous
#include <cuda_runtime.h>
#include <math.h>
#include <stdint.h>

// ---------------------------------------------------------------------------
// Problem constants (fixed by setup_inputs)
#define BB   2
#define TT   2048
#define DIMC 1024
#define HH   16
#define DHH  64
#define LL   3
#define KKS  4
#define TOTROWS 7168           // 4096 + 2048 + 1024 rows of K/V

// GEMM tiling: 128x128 CTA tile, BK=32, 3-stage cp.async, 8 warps (64x32 each),
// <=128 regs/thread so 2 CTAs co-reside per SM. Fragments via ldmatrix,
// tf32-RN rounding applied to A fragments in-register (no pre-rounded copy).
#define BM 128
#define BN 128
#define BK 32
#define NSTAGE 3
#define NT (DIMC / BK)          // 32 k-iterations
#define ROWF 36                 // smem row stride in floats (144B)
#define TILEF (BM * ROWF)       // 4608 floats per tile (A or B)
#define STAGEF (2 * TILEF)      // 9216 floats
#define GEMM_SMEM (NSTAGE * STAGEF * 4)   // 110592 bytes -> 2 CTAs/SM

// ---------------------------------------------------------------------------
// scratch (device globals; no allocation allowed)
__device__ float g_q     [BB * TT * DIMC];
__device__ float g_off   [BB * TT * HH * LL * KKS];
__device__ float g_k     [TOTROWS * DIMC];
__device__ float g_v     [TOTROWS * DIMC];
__device__ float g_ao    [BB * TT * DIMC];
__device__ float g_WqkvoT[4 * DIMC * DIMC];          // [Wq;Wk;Wv;Wo] transposed [N,K]

// ---------------------------------------------------------------------------
__device__ __forceinline__ float rna_tf32(float x) {
    float r;
    asm("cvt.rna.tf32.f32 %0, %1;" : "=f"(r) : "f"(x));
    return r;
}
__device__ __forceinline__ uint32_t rna_tf32_u(uint32_t x) {
    uint32_t r;
    asm("cvt.rna.tf32.f32 %0, %1;" : "=r"(r) : "r"(x));
    return r;
}
__device__ __forceinline__ uint32_t smem_u32(const void* p) {
    uint32_t a;
    asm("{ .reg .u64 t; cvta.to.shared.u64 t, %1; cvt.u32.u64 %0, t; }"
        : "=r"(a) : "l"(p));
    return a;
}
__device__ __forceinline__ void cp_async16(uint32_t dst, const void* src) {
    asm volatile("cp.async.cg.shared.global [%0], [%1], 16;"
                 :: "r"(dst), "l"(src) : "memory");
}
__device__ __forceinline__ void cp_commit() {
    asm volatile("cp.async.commit_group;" ::: "memory");
}
template <int N>
__device__ __forceinline__ void cp_wait() {
    asm volatile("cp.async.wait_group %0;" :: "n"(N) : "memory");
}
__device__ __forceinline__ void ldsm_x4(uint32_t& r0, uint32_t& r1,
                                        uint32_t& r2, uint32_t& r3, uint32_t addr) {
    asm volatile("ldmatrix.sync.aligned.m8n8.x4.shared.b16 {%0,%1,%2,%3}, [%4];"
                 : "=r"(r0), "=r"(r1), "=r"(r2), "=r"(r3) : "r"(addr));
}
__device__ __forceinline__ void mma_tf32(float& d0, float& d1, float& d2, float& d3,
                                         uint32_t a0, uint32_t a1, uint32_t a2, uint32_t a3,
                                         uint32_t b0, uint32_t b1) {
    asm volatile(
        "mma.sync.aligned.m16n8k8.row.col.f32.tf32.tf32.f32 "
        "{%0,%1,%2,%3}, {%4,%5,%6,%7}, {%8,%9}, {%0,%1,%2,%3};"
        : "+f"(d0), "+f"(d1), "+f"(d2), "+f"(d3)
        : "r"(a0), "r"(a1), "r"(a2), "r"(a3), "r"(b0), "r"(b1));
}

// ---------------------------------------------------------------------------
// tf32 mma.sync GEMM, 128x128 tile, 8 warps (2x4, 64x32 warp tiles),
// ldmatrix fragment loads + in-register RN rounding of A fragments,
// segmented output routing (8 CTAs per 1024-col segment).
__global__ __launch_bounds__(256, 2) void gemm_tf32(
    const float* __restrict__ A, const float* __restrict__ BT,
    const float* __restrict__ b0, const float* __restrict__ b1,
    const float* __restrict__ b2,
    float* __restrict__ C0, float* __restrict__ C1, float* __restrict__ C2) {
    extern __shared__ float smem[];

    int tid  = threadIdx.x;
    int wid  = tid >> 5, lane = tid & 31;
    int gid  = lane >> 2, tg = lane & 3;
    int wm   = wid >> 2;          // 0..1 (64-row band)
    int wn   = wid & 3;           // 0..3 (32-col band)
    int m0   = blockIdx.y * BM;

    int seg  = blockIdx.x >> 3;
    int ncol = (blockIdx.x & 7) * BN;
    const float* bias = (seg == 0) ? b0 : (seg == 1) ? b1 : b2;
    float* C          = (seg == 0) ? C0 : (seg == 1) ? C1 : C2;

    uint32_t sbase = smem_u32(smem);

    const float* Abase = A  + (size_t)m0 * DIMC;
    const float* Bbase = BT + (size_t)blockIdx.x * BN * DIMC;

    // ldmatrix lane address offsets (see round-11 notes).
    int lrow = lane & 7;
    int lm8  = (lane >> 3) & 1;
    int lk4  = (lane >> 4) & 1;
    uint32_t a_off[4];
#pragma unroll
    for (int mi = 0; mi < 4; mi++) {
        int row = wm * 64 + mi * 16 + lm8 * 8 + lrow;
        a_off[mi] = (uint32_t)((row * ROWF + lk4 * 4) * 4);
    }
    uint32_t bt_off[2];
#pragma unroll
    for (int p = 0; p < 2; p++) {
        int n = wn * 32 + p * 16 + lk4 * 8 + lrow;
        bt_off[p] = (uint32_t)((n * ROWF + lm8 * 4) * 4);
    }

    float acc[4][4][4];
#pragma unroll
    for (int mi = 0; mi < 4; mi++)
#pragma unroll
        for (int ni = 0; ni < 4; ni++)
#pragma unroll
            for (int r = 0; r < 4; r++) acc[mi][ni][r] = 0.f;

#define ISSUE_STAGE(pt) do {                                                   \
        uint32_t sa_  = sbase + (((pt) % NSTAGE) * STAGEF) * 4;                \
        uint32_t sbB_ = sa_ + TILEF * 4;                                       \
        _Pragma("unroll")                                                      \
        for (int i_ = 0; i_ < 4; i_++) {                                       \
            int cid_ = i_ * 256 + tid;                                         \
            int r_ = cid_ >> 3, c_ = cid_ & 7;                                 \
            cp_async16(sa_ + (r_ * ROWF + c_ * 4) * 4,                         \
                       Abase + (size_t)r_ * DIMC + (pt) * BK + c_ * 4);        \
            cp_async16(sbB_ + (r_ * ROWF + c_ * 4) * 4,                        \
                       Bbase + (size_t)r_ * DIMC + (pt) * BK + c_ * 4);        \
        }                                                                      \
        cp_commit();                                                           \
    } while (0)

    ISSUE_STAGE(0);
    ISSUE_STAGE(1);

    for (int kt = 0; kt < NT; kt++) {
        if (kt + 2 < NT) cp_wait<1>(); else cp_wait<0>();
        __syncthreads();   // stage kt visible AND stage (kt+2)%3 free

        if (kt + 2 < NT) ISSUE_STAGE(kt + 2);

        uint32_t abase = sbase + ((kt % NSTAGE) * STAGEF) * 4;
        uint32_t bbase = abase + TILEF * 4;

#pragma unroll
        for (int j = 0; j < 4; j++) {
            uint32_t af[4][4], bf[4][2];
            uint32_t jb = (uint32_t)(j * 32);
#pragma unroll
            for (int mi = 0; mi < 4; mi++) {
                ldsm_x4(af[mi][0], af[mi][1], af[mi][2], af[mi][3],
                        abase + a_off[mi] + jb);
                af[mi][0] = rna_tf32_u(af[mi][0]);
                af[mi][1] = rna_tf32_u(af[mi][1]);
                af[mi][2] = rna_tf32_u(af[mi][2]);
                af[mi][3] = rna_tf32_u(af[mi][3]);
            }
#pragma unroll
            for (int p = 0; p < 2; p++)
                ldsm_x4(bf[2 * p][0], bf[2 * p][1], bf[2 * p + 1][0],
                        bf[2 * p + 1][1], bbase + bt_off[p] + jb);
#pragma unroll
            for (int mi = 0; mi < 4; mi++)
#pragma unroll
                for (int ni = 0; ni < 4; ni++)
                    mma_tf32(acc[mi][ni][0], acc[mi][ni][1],
                             acc[mi][ni][2], acc[mi][ni][3],
                             af[mi][0], af[mi][1], af[mi][2], af[mi][3],
                             bf[ni][0], bf[ni][1]);
        }
    }

#pragma unroll
    for (int mi = 0; mi < 4; mi++) {
        int r0 = m0 + wm * 64 + mi * 16 + gid;
#pragma unroll
        for (int ni = 0; ni < 4; ni++) {
            int c = ncol + wn * 32 + ni * 8 + tg * 2;
            float bx = bias[c], by = bias[c + 1];
            float2 o0 = make_float2(acc[mi][ni][0] + bx, acc[mi][ni][1] + by);
            float2 o1 = make_float2(acc[mi][ni][2] + bx, acc[mi][ni][3] + by);
            *(float2*)&C[(size_t)r0 * DIMC + c] = o0;
            *(float2*)&C[(size_t)(r0 + 8) * DIMC + c] = o1;
        }
    }
#undef ISSUE_STAGE
}

// ---------------------------------------------------------------------------
// fp32 SGEMM (exact) for the offset projection: C[M,N] = A@W + bias, N=192
__global__ __launch_bounds__(256) void sgemm_bias(
    int M, int N, int K,
    const float* __restrict__ A, const float* __restrict__ W,
    const float* __restrict__ bias, float* __restrict__ C) {
    __shared__ float As[8][128];
    __shared__ float Bs[8][128];

    int tid = threadIdx.x;
    int bm = blockIdx.y, bn = blockIdx.x;

    int aRow = tid >> 1;
    int aCol = (tid & 1) * 4;
    int bRow = tid >> 5;
    int bCol = (tid & 31) * 4;
    int wcol = bn * 128 + bCol;

    int tRow = (tid >> 4) * 8;
    int tCol = (tid & 15) * 8;

    const float* Ab = A + (size_t)(bm * 128 + aRow) * K + aCol;

    float acc[8][8];
#pragma unroll
    for (int i = 0; i < 8; i++)
#pragma unroll
        for (int j = 0; j < 8; j++) acc[i][j] = 0.f;

    for (int k0 = 0; k0 < K; k0 += 8) {
        float4 av = *(const float4*)(Ab + k0);
        As[aCol + 0][aRow] = av.x;
        As[aCol + 1][aRow] = av.y;
        As[aCol + 2][aRow] = av.z;
        As[aCol + 3][aRow] = av.w;
        float4 wv = make_float4(0.f, 0.f, 0.f, 0.f);
        if (wcol < N)
            wv = *(const float4*)(W + (size_t)(k0 + bRow) * N + wcol);
        *(float4*)&Bs[bRow][bCol] = wv;
        __syncthreads();
#pragma unroll
        for (int kk = 0; kk < 8; kk++) {
            float4 a0 = *(const float4*)&As[kk][tRow];
            float4 a1 = *(const float4*)&As[kk][tRow + 4];
            float4 b0 = *(const float4*)&Bs[kk][tCol];
            float4 b1 = *(const float4*)&Bs[kk][tCol + 4];
            float av8[8] = {a0.x, a0.y, a0.z, a0.w, a1.x, a1.y, a1.z, a1.w};
            float bv8[8] = {b0.x, b0.y, b0.z, b0.w, b1.x, b1.y, b1.z, b1.w};
#pragma unroll
            for (int i = 0; i < 8; i++)
#pragma unroll
                for (int j = 0; j < 8; j++) acc[i][j] += av8[i] * bv8[j];
        }
        __syncthreads();
    }

#pragma unroll
    for (int i = 0; i < 8; i++) {
        size_t row = (size_t)(bm * 128 + tRow + i);
#pragma unroll
        for (int j = 0; j < 8; j += 4) {
            int col = bn * 128 + tCol + j;
            if (col < N) {
                float4 o;
                o.x = acc[i][j + 0] + bias[col + 0];
                o.y = acc[i][j + 1] + bias[col + 1];
                o.z = acc[i][j + 2] + bias[col + 2];
                o.w = acc[i][j + 3] + bias[col + 3];
                *(float4*)&C[row * N + col] = o;
            }
        }
    }
}

// ---------------------------------------------------------------------------
// fused K/V pyramid: one launch, 4 jobs via blockIdx.z, all reading level 0.
//   z=0: K level1 (pair avg)      z=1: V level1
//   z=2: K level2 (4-row avg, bitwise == two-stage)   z=3: V level2
__global__ void downsample_all(const float* __restrict__ k0,
                               const float* __restrict__ v0,
                               float* __restrict__ k1, float* __restrict__ v1,
                               float* __restrict__ k2, float* __restrict__ v2) {
    int z = blockIdx.z;
    int lvl2 = z >> 1;
    int Tout = lvl2 ? 512 : 1024;
    int n = BB * Tout * (DIMC / 4);
    int i = blockIdx.x * blockDim.x + threadIdx.x;
    if (i >= n) return;
    int c4 = i % (DIMC / 4);
    int t  = (i / (DIMC / 4)) % Tout;
    int b  = i / (Tout * (DIMC / 4));
    const float4* in4 = (const float4*)((z & 1) ? v0 : k0);
    float4* out4 = (float4*)(lvl2 ? ((z & 1) ? v2 : k2) : ((z & 1) ? v1 : k1));
    int Tin = 2048;
    int t0 = t << (1 + lvl2);
    float4 a = in4[((size_t)b * Tin + t0)     * (DIMC / 4) + c4];
    float4 c = in4[((size_t)b * Tin + t0 + 1) * (DIMC / 4) + c4];
    float4 r;
    if (!lvl2) {
        r.x = 0.5f * (a.x + c.x);
        r.y = 0.5f * (a.y + c.y);
        r.z = 0.5f * (a.z + c.z);
        r.w = 0.5f * (a.w + c.w);
    } else {
        float4 d = in4[((size_t)b * Tin + t0 + 2) * (DIMC / 4) + c4];
        float4 e = in4[((size_t)b * Tin + t0 + 3) * (DIMC / 4) + c4];
        r.x = 0.5f * (0.5f * (a.x + c.x) + 0.5f * (d.x + e.x));
        r.y = 0.5f * (0.5f * (a.y + c.y) + 0.5f * (d.y + e.y));
        r.z = 0.5f * (0.5f * (a.z + c.z) + 0.5f * (d.z + e.z));
        r.w = 0.5f * (0.5f * (a.w + c.w) + 0.5f * (d.w + e.w));
    }
    out4[i] = r;
}

// fused transpose + tf32 round for 4 weights: WT[z][n][k] = rna(W_z[k][n])
__global__ void transpose_rna4(const float* __restrict__ W0, const float* __restrict__ W1,
                               const float* __restrict__ W2, const float* __restrict__ W3,
                               float* __restrict__ WT) {
    __shared__ float tile[32][33];
    int z  = blockIdx.z;
    const float* W = (z == 0) ? W0 : (z == 1) ? W1 : (z == 2) ? W2 : W3;
    float* WTo = WT + (size_t)z * DIMC * DIMC;
    int k0 = blockIdx.x * 32, n0 = blockIdx.y * 32;
    int tx = threadIdx.x, ty = threadIdx.y;   // 32 x 8
#pragma unroll
    for (int i = ty; i < 32; i += 8)
        tile[i][tx] = rna_tf32(W[(size_t)(k0 + i) * DIMC + n0 + tx]);
    __syncthreads();
#pragma unroll
    for (int i = ty; i < 32; i += 8)
        WTo[(size_t)(n0 + i) * DIMC + k0 + tx] = tile[tx][i];
}

// ---------------------------------------------------------------------------
// attention: one warp per (b,t,h); lane = RoPE pair (lane, lane+32).
// MUFU sincos (fast path); batched loads; batched shfl reductions.
__global__ __launch_bounds__(256) void attn_kernel(
    const float* __restrict__ q, const float* __restrict__ offr,
    const float* __restrict__ kall, const float* __restrict__ vall,
    float* __restrict__ out) {
    int warp = (blockIdx.x * blockDim.x + threadIdx.x) >> 5;
    int lane = threadIdx.x & 31;
    int h = warp % HH;
    int t = (warp / HH) % TT;
    int b = warp / (HH * TT);
    if (b >= BB) return;

    const float LOG1E4 = 9.210340371976184f;
    float inv_freq = __expf(-(float)lane * (LOG1E4 / 32.0f));

    size_t qbase = ((size_t)(b * TT + t) * DIMC) + h * DHH + lane;
    float q1 = q[qbase], q2 = q[qbase + 32];
    float sq, cq;
    sincosf((float)t * inv_freq, &sq, &cq);   // exact path for q (13->12 fast ones below)
    float q1r = q1 * cq - q2 * sq;
    float q2r = q1 * sq + q2 * cq;

    float refp = (float)t * (1.0f / (float)(TT - 1));

    float p[LL * KKS];
    float vs1[LL * KKS], vs2[LL * KKS];

    const int TsA[3]     = {2048, 1024, 512};
    const int rowbase[3] = {0, 4096, 6144};
    int offb = ((b * TT + t) * HH + h) * (LL * KKS);

    float idxA[LL * KKS], w1A[LL * KKS];
    int   o0A[LL * KKS], o1A[LL * KKS];
#pragma unroll
    for (int l = 0; l < LL; l++) {
        int Ts = TsA[l];
        float Tm1 = (float)(Ts - 1);
        int lvb = (rowbase[l] + b * Ts) * DIMC + h * DHH + lane;
#pragma unroll
        for (int k = 0; k < KKS; k++) {
            int li = l * KKS + k;
            float ofv = tanhf(offr[offb + li]) * 0.25f;
            float s = fminf(fmaxf(refp + ofv, 0.f), 1.f);
            float idx = fminf(s * Tm1, Tm1 - 1e-6f);
            int i0 = (int)idx;
            int i1 = min(i0 + 1, Ts - 1);
            idxA[li] = idx;
            w1A[li]  = idx - (float)i0;
            o0A[li]  = lvb + i0 * DIMC;
            o1A[li]  = lvb + i1 * DIMC;
        }
    }

#pragma unroll
    for (int li = 0; li < LL * KKS; li++) {
        float w1 = w1A[li], w0 = 1.f - w1;
        const float* k0p = kall + o0A[li];
        const float* k1p = kall + o1A[li];
        const float* v0p = vall + o0A[li];
        const float* v1p = vall + o1A[li];
        float k0a = k0p[0],  k1a = k1p[0];
        float k0b = k0p[32], k1b = k1p[32];
        float v0a = v0p[0],  v1a = v1p[0];
        float v0b = v0p[32], v1b = v1p[32];

        float ks1 = w0 * k0a + w1 * k1a;
        float ks2 = w0 * k0b + w1 * k1b;
        vs1[li]   = w0 * v0a + w1 * v1a;
        vs2[li]   = w0 * v0b + w1 * v1b;

        float si, co;
        __sincosf(idxA[li] * inv_freq, &si, &co);   // MUFU fast path
        float kr1 = ks1 * co - ks2 * si;
        float kr2 = ks1 * si + ks2 * co;
        p[li] = q1r * kr1 + q2r * kr2;
    }

#pragma unroll
    for (int d = 16; d > 0; d >>= 1) {
#pragma unroll
        for (int li = 0; li < LL * KKS; li++)
            p[li] += __shfl_xor_sync(0xffffffffu, p[li], d);
    }

    float m = p[0] * 0.125f;
#pragma unroll
    for (int i = 1; i < LL * KKS; i++) m = fmaxf(m, p[i] * 0.125f);
    float den = 0.f;
#pragma unroll
    for (int i = 0; i < LL * KKS; i++) {
        p[i] = __expf(p[i] * 0.125f - m);
        den += p[i];
    }
    float rden = 1.f / den;
    float o1 = 0.f, o2 = 0.f;
#pragma unroll
    for (int i = 0; i < LL * KKS; i++) {
        float a = p[i] * rden;
        o1 += a * vs1[i];
        o2 += a * vs2[i];
    }
    out[qbase]      = o1;   // GEMM rounds A-fragments in-register now
    out[qbase + 32] = o2;
}

// ---------------------------------------------------------------------------
extern "C" void kernel_launch(void* const* d_in, const int* in_sizes, int n_in,
                              void* d_out, int out_size) {
    const float* x    = (const float*)d_in[0];
    const float* Wq   = (const float*)d_in[2];
    const float* bq   = (const float*)d_in[3];
    const float* Wk   = (const float*)d_in[4];
    const float* bk   = (const float*)d_in[5];
    const float* Wv   = (const float*)d_in[6];
    const float* bv   = (const float*)d_in[7];
    const float* Woff = (const float*)d_in[8];
    const float* boff = (const float*)d_in[9];
    const float* Wo   = (const float*)d_in[10];
    const float* bo   = (const float*)d_in[11];
    float* out = (float*)d_out;

    float *qg, *offg, *kg, *vg, *aog, *wT;
    cudaGetSymbolAddress((void**)&qg,   g_q);
    cudaGetSymbolAddress((void**)&offg, g_off);
    cudaGetSymbolAddress((void**)&kg,   g_k);
    cudaGetSymbolAddress((void**)&vg,   g_v);
    cudaGetSymbolAddress((void**)&aog,  g_ao);
    cudaGetSymbolAddress((void**)&wT,   g_WqkvoT);

    cudaFuncSetAttribute(gemm_tf32, cudaFuncAttributeMaxDynamicSharedMemorySize,
                         GEMM_SMEM);

    // side stream + events for capture-legal fork/join (resources only)
    static cudaStream_t s_side = nullptr;
    static cudaEvent_t e_fork = nullptr, e_join = nullptr;
    if (s_side == nullptr) {
        cudaStreamCreateWithFlags(&s_side, cudaStreamNonBlocking);
        cudaEventCreateWithFlags(&e_fork, cudaEventDisableTiming);
        cudaEventCreateWithFlags(&e_join, cudaEventDisableTiming);
    }

    // fork: offset projection (exact fp32, depends only on x, feeds only attn)
    cudaEventRecord(e_fork, 0);
    cudaStreamWaitEvent(s_side, e_fork, 0);
    {
        dim3 grid(2, (BB * TT) / 128);
        sgemm_bias<<<grid, 256, 0, s_side>>>(BB * TT, HH * LL * KKS, DIMC,
                                             x, Woff, boff, offg);
        cudaEventRecord(e_join, s_side);
    }

    // main stream: transpose+round weights (x is consumed raw by the GEMM,
    // which RN-rounds A fragments in-register)
    transpose_rna4<<<dim3(32, 32, 4), dim3(32, 8)>>>(Wq, Wk, Wv, Wo, wT);

    // fused Q/K/V level-0 projection: x @ [Wq|Wk|Wv] (N=3072)
    gemm_tf32<<<dim3(24, 32), 256, GEMM_SMEM>>>(
        x, wT, bq, bk, bv, qg, kg, vg);

    // K/V pyramid levels (both from level 0; one launch)
    {
        int n1 = BB * 1024 * (DIMC / 4);
        int blocks = (n1 + 255) / 256;
        downsample_all<<<dim3(blocks, 1, 4), 256>>>(
            kg, vg,
            kg + (size_t)4096 * DIMC, vg + (size_t)4096 * DIMC,
            kg + (size_t)6144 * DIMC, vg + (size_t)6144 * DIMC);
    }

    // join: attention needs the offsets from the side stream
    cudaStreamWaitEvent(0, e_join, 0);

    // deformable attention
    {
        int warps = BB * TT * HH;
        attn_kernel<<<warps / 8, 256>>>(qg, offg, kg, vg, aog);
    }

    // output projection -> d_out  (Wo is segment 3 of wT)
    gemm_tf32<<<dim3(8, 32), 256, GEMM_SMEM>>>(
        aog, wT + (size_t)3 * DIMC * DIMC, bo, bo, bo, out, out, out);
}

// round 13
// speedup vs baseline: 1.3908x; 1.0239x over previous
#include <cuda_runtime.h>
#include <math.h>
#include <stdint.h>

// ---------------------------------------------------------------------------
// Problem constants (fixed by setup_inputs)
#define BB   2
#define TT   2048
#define DIMC 1024
#define HH   16
#define DHH  64
#define LL   3
#define KKS  4
#define TOTROWS 7168           // 4096 + 2048 + 1024 rows of K/V

// GEMM tiling: 128x128 CTA tile, BK=32, 3-stage cp.async, 4 warps (64x64 each),
// 128 threads, 2 CTAs/SM. Crossbar-minimal: fragment traffic 128KB/SM/kt.
#define BM 128
#define BN 128
#define BK 32
#define NSTAGE 3
#define NT (DIMC / BK)          // 32 k-iterations
#define ROWF 36                 // smem row stride in floats (144B)
#define TILEF (BM * ROWF)       // 4608 floats per tile (A or B)
#define STAGEF (2 * TILEF)      // 9216 floats
#define GEMM_SMEM (NSTAGE * STAGEF * 4)   // 110592 bytes -> 2 CTAs/SM

// ---------------------------------------------------------------------------
// scratch (device globals; no allocation allowed)
__device__ float g_q     [BB * TT * DIMC];
__device__ float g_off   [BB * TT * HH * LL * KKS];
__device__ float g_k     [TOTROWS * DIMC];
__device__ float g_v     [TOTROWS * DIMC];
__device__ float g_ao    [BB * TT * DIMC];
__device__ float g_WqkvoT[4 * DIMC * DIMC];          // [Wq;Wk;Wv;Wo] transposed [N,K]

// ---------------------------------------------------------------------------
__device__ __forceinline__ float rna_tf32(float x) {
    float r;
    asm("cvt.rna.tf32.f32 %0, %1;" : "=f"(r) : "f"(x));
    return r;
}
__device__ __forceinline__ uint32_t rna_tf32_u(uint32_t x) {
    uint32_t r;
    asm("cvt.rna.tf32.f32 %0, %1;" : "=r"(r) : "r"(x));
    return r;
}
__device__ __forceinline__ uint32_t smem_u32(const void* p) {
    uint32_t a;
    asm("{ .reg .u64 t; cvta.to.shared.u64 t, %1; cvt.u32.u64 %0, t; }"
        : "=r"(a) : "l"(p));
    return a;
}
__device__ __forceinline__ void cp_async16(uint32_t dst, const void* src) {
    asm volatile("cp.async.cg.shared.global [%0], [%1], 16;"
                 :: "r"(dst), "l"(src) : "memory");
}
__device__ __forceinline__ void cp_commit() {
    asm volatile("cp.async.commit_group;" ::: "memory");
}
template <int N>
__device__ __forceinline__ void cp_wait() {
    asm volatile("cp.async.wait_group %0;" :: "n"(N) : "memory");
}
__device__ __forceinline__ void ldsm_x4(uint32_t& r0, uint32_t& r1,
                                        uint32_t& r2, uint32_t& r3, uint32_t addr) {
    asm volatile("ldmatrix.sync.aligned.m8n8.x4.shared.b16 {%0,%1,%2,%3}, [%4];"
                 : "=r"(r0), "=r"(r1), "=r"(r2), "=r"(r3) : "r"(addr));
}
__device__ __forceinline__ void mma_tf32(float& d0, float& d1, float& d2, float& d3,
                                         uint32_t a0, uint32_t a1, uint32_t a2, uint32_t a3,
                                         uint32_t b0, uint32_t b1) {
    asm volatile(
        "mma.sync.aligned.m16n8k8.row.col.f32.tf32.tf32.f32 "
        "{%0,%1,%2,%3}, {%4,%5,%6,%7}, {%8,%9}, {%0,%1,%2,%3};"
        : "+f"(d0), "+f"(d1), "+f"(d2), "+f"(d3)
        : "r"(a0), "r"(a1), "r"(a2), "r"(a3), "r"(b0), "r"(b1));
}

// ---------------------------------------------------------------------------
// tf32 mma.sync GEMM, 128x128 tile, 4 warps (2x2, 64x64 warp tiles),
// ldmatrix fragment loads + in-register RN rounding of A fragments,
// segmented output routing (8 CTAs per 1024-col segment).
__global__ __launch_bounds__(128, 2) void gemm_tf32(
    const float* __restrict__ A, const float* __restrict__ BT,
    const float* __restrict__ b0, const float* __restrict__ b1,
    const float* __restrict__ b2,
    float* __restrict__ C0, float* __restrict__ C1, float* __restrict__ C2) {
    extern __shared__ float smem[];

    int tid  = threadIdx.x;
    int wid  = tid >> 5, lane = tid & 31;
    int gid  = lane >> 2, tg = lane & 3;
    int wm   = wid >> 1;          // 0..1 (64-row band)
    int wn   = wid & 1;           // 0..1 (64-col band)
    int m0   = blockIdx.y * BM;

    int seg  = blockIdx.x >> 3;
    int ncol = (blockIdx.x & 7) * BN;
    const float* bias = (seg == 0) ? b0 : (seg == 1) ? b1 : b2;
    float* C          = (seg == 0) ? C0 : (seg == 1) ? C1 : C2;

    uint32_t sbase = smem_u32(smem);

    const float* Abase = A  + (size_t)m0 * DIMC;
    const float* Bbase = BT + (size_t)blockIdx.x * BN * DIMC;

    // ldmatrix lane address offsets.
    int lrow = lane & 7;
    int lm8  = (lane >> 3) & 1;
    int lk4  = (lane >> 4) & 1;
    uint32_t a_off[4];
#pragma unroll
    for (int mi = 0; mi < 4; mi++) {
        int row = wm * 64 + mi * 16 + lm8 * 8 + lrow;
        a_off[mi] = (uint32_t)((row * ROWF + lk4 * 4) * 4);
    }
    // B ni-pairs p=0..3: m0=(n+0..7,k0..3) m1=(n+0..7,k4..7)
    //                    m2=(n+8..15,k0..3) m3=(n+8..15,k4..7)
    uint32_t bt_off[4];
#pragma unroll
    for (int p = 0; p < 4; p++) {
        int n = wn * 64 + p * 16 + lk4 * 8 + lrow;
        bt_off[p] = (uint32_t)((n * ROWF + lm8 * 4) * 4);
    }

    float acc[4][8][4];
#pragma unroll
    for (int mi = 0; mi < 4; mi++)
#pragma unroll
        for (int ni = 0; ni < 8; ni++)
#pragma unroll
            for (int r = 0; r < 4; r++) acc[mi][ni][r] = 0.f;

    // per-stage async copy: A tile 8 chunks/thread, B tile 8 chunks/thread
#define ISSUE_STAGE(pt) do {                                                   \
        uint32_t sa_  = sbase + (((pt) % NSTAGE) * STAGEF) * 4;                \
        uint32_t sbB_ = sa_ + TILEF * 4;                                       \
        _Pragma("unroll")                                                      \
        for (int i_ = 0; i_ < 8; i_++) {                                       \
            int cid_ = i_ * 128 + tid;                                         \
            int r_ = cid_ >> 3, c_ = cid_ & 7;                                 \
            cp_async16(sa_ + (r_ * ROWF + c_ * 4) * 4,                         \
                       Abase + (size_t)r_ * DIMC + (pt) * BK + c_ * 4);        \
            cp_async16(sbB_ + (r_ * ROWF + c_ * 4) * 4,                        \
                       Bbase + (size_t)r_ * DIMC + (pt) * BK + c_ * 4);        \
        }                                                                      \
        cp_commit();                                                           \
    } while (0)

    ISSUE_STAGE(0);
    ISSUE_STAGE(1);

    for (int kt = 0; kt < NT; kt++) {
        if (kt + 2 < NT) cp_wait<1>(); else cp_wait<0>();
        __syncthreads();   // stage kt visible AND stage (kt+2)%3 free

        if (kt + 2 < NT) ISSUE_STAGE(kt + 2);

        uint32_t abase = sbase + ((kt % NSTAGE) * STAGEF) * 4;
        uint32_t bbase = abase + TILEF * 4;

#pragma unroll
        for (int j = 0; j < 4; j++) {
            uint32_t af[4][4], bf[8][2];
            uint32_t jb = (uint32_t)(j * 32);
#pragma unroll
            for (int mi = 0; mi < 4; mi++) {
                ldsm_x4(af[mi][0], af[mi][1], af[mi][2], af[mi][3],
                        abase + a_off[mi] + jb);
                af[mi][0] = rna_tf32_u(af[mi][0]);
                af[mi][1] = rna_tf32_u(af[mi][1]);
                af[mi][2] = rna_tf32_u(af[mi][2]);
                af[mi][3] = rna_tf32_u(af[mi][3]);
            }
#pragma unroll
            for (int p = 0; p < 4; p++)
                ldsm_x4(bf[2 * p][0], bf[2 * p][1], bf[2 * p + 1][0],
                        bf[2 * p + 1][1], bbase + bt_off[p] + jb);
#pragma unroll
            for (int mi = 0; mi < 4; mi++)
#pragma unroll
                for (int ni = 0; ni < 8; ni++)
                    mma_tf32(acc[mi][ni][0], acc[mi][ni][1],
                             acc[mi][ni][2], acc[mi][ni][3],
                             af[mi][0], af[mi][1], af[mi][2], af[mi][3],
                             bf[ni][0], bf[ni][1]);
        }
    }

#pragma unroll
    for (int mi = 0; mi < 4; mi++) {
        int r0 = m0 + wm * 64 + mi * 16 + gid;
#pragma unroll
        for (int ni = 0; ni < 8; ni++) {
            int c = ncol + wn * 64 + ni * 8 + tg * 2;
            float bx = bias[c], by = bias[c + 1];
            float2 o0 = make_float2(acc[mi][ni][0] + bx, acc[mi][ni][1] + by);
            float2 o1 = make_float2(acc[mi][ni][2] + bx, acc[mi][ni][3] + by);
            *(float2*)&C[(size_t)r0 * DIMC + c] = o0;
            *(float2*)&C[(size_t)(r0 + 8) * DIMC + c] = o1;
        }
    }
#undef ISSUE_STAGE
}

// ---------------------------------------------------------------------------
// fp32 SGEMM (exact) for the offset projection: C[M,N] = A@W + bias, N=192
__global__ __launch_bounds__(256) void sgemm_bias(
    int M, int N, int K,
    const float* __restrict__ A, const float* __restrict__ W,
    const float* __restrict__ bias, float* __restrict__ C) {
    __shared__ float As[8][128];
    __shared__ float Bs[8][128];

    int tid = threadIdx.x;
    int bm = blockIdx.y, bn = blockIdx.x;

    int aRow = tid >> 1;
    int aCol = (tid & 1) * 4;
    int bRow = tid >> 5;
    int bCol = (tid & 31) * 4;
    int wcol = bn * 128 + bCol;

    int tRow = (tid >> 4) * 8;
    int tCol = (tid & 15) * 8;

    const float* Ab = A + (size_t)(bm * 128 + aRow) * K + aCol;

    float acc[8][8];
#pragma unroll
    for (int i = 0; i < 8; i++)
#pragma unroll
        for (int j = 0; j < 8; j++) acc[i][j] = 0.f;

    for (int k0 = 0; k0 < K; k0 += 8) {
        float4 av = *(const float4*)(Ab + k0);
        As[aCol + 0][aRow] = av.x;
        As[aCol + 1][aRow] = av.y;
        As[aCol + 2][aRow] = av.z;
        As[aCol + 3][aRow] = av.w;
        float4 wv = make_float4(0.f, 0.f, 0.f, 0.f);
        if (wcol < N)
            wv = *(const float4*)(W + (size_t)(k0 + bRow) * N + wcol);
        *(float4*)&Bs[bRow][bCol] = wv;
        __syncthreads();
#pragma unroll
        for (int kk = 0; kk < 8; kk++) {
            float4 a0 = *(const float4*)&As[kk][tRow];
            float4 a1 = *(const float4*)&As[kk][tRow + 4];
            float4 b0 = *(const float4*)&Bs[kk][tCol];
            float4 b1 = *(const float4*)&Bs[kk][tCol + 4];
            float av8[8] = {a0.x, a0.y, a0.z, a0.w, a1.x, a1.y, a1.z, a1.w};
            float bv8[8] = {b0.x, b0.y, b0.z, b0.w, b1.x, b1.y, b1.z, b1.w};
#pragma unroll
            for (int i = 0; i < 8; i++)
#pragma unroll
                for (int j = 0; j < 8; j++) acc[i][j] += av8[i] * bv8[j];
        }
        __syncthreads();
    }

#pragma unroll
    for (int i = 0; i < 8; i++) {
        size_t row = (size_t)(bm * 128 + tRow + i);
#pragma unroll
        for (int j = 0; j < 8; j += 4) {
            int col = bn * 128 + tCol + j;
            if (col < N) {
                float4 o;
                o.x = acc[i][j + 0] + bias[col + 0];
                o.y = acc[i][j + 1] + bias[col + 1];
                o.z = acc[i][j + 2] + bias[col + 2];
                o.w = acc[i][j + 3] + bias[col + 3];
                *(float4*)&C[row * N + col] = o;
            }
        }
    }
}

// ---------------------------------------------------------------------------
// fused K/V pyramid: one launch, 4 jobs via blockIdx.z, all reading level 0.
__global__ void downsample_all(const float* __restrict__ k0,
                               const float* __restrict__ v0,
                               float* __restrict__ k1, float* __restrict__ v1,
                               float* __restrict__ k2, float* __restrict__ v2) {
    int z = blockIdx.z;
    int lvl2 = z >> 1;
    int Tout = lvl2 ? 512 : 1024;
    int n = BB * Tout * (DIMC / 4);
    int i = blockIdx.x * blockDim.x + threadIdx.x;
    if (i >= n) return;
    int c4 = i % (DIMC / 4);
    int t  = (i / (DIMC / 4)) % Tout;
    int b  = i / (Tout * (DIMC / 4));
    const float4* in4 = (const float4*)((z & 1) ? v0 : k0);
    float4* out4 = (float4*)(lvl2 ? ((z & 1) ? v2 : k2) : ((z & 1) ? v1 : k1));
    int Tin = 2048;
    int t0 = t << (1 + lvl2);
    float4 a = in4[((size_t)b * Tin + t0)     * (DIMC / 4) + c4];
    float4 c = in4[((size_t)b * Tin + t0 + 1) * (DIMC / 4) + c4];
    float4 r;
    if (!lvl2) {
        r.x = 0.5f * (a.x + c.x);
        r.y = 0.5f * (a.y + c.y);
        r.z = 0.5f * (a.z + c.z);
        r.w = 0.5f * (a.w + c.w);
    } else {
        float4 d = in4[((size_t)b * Tin + t0 + 2) * (DIMC / 4) + c4];
        float4 e = in4[((size_t)b * Tin + t0 + 3) * (DIMC / 4) + c4];
        r.x = 0.5f * (0.5f * (a.x + c.x) + 0.5f * (d.x + e.x));
        r.y = 0.5f * (0.5f * (a.y + c.y) + 0.5f * (d.y + e.y));
        r.z = 0.5f * (0.5f * (a.z + c.z) + 0.5f * (d.z + e.z));
        r.w = 0.5f * (0.5f * (a.w + c.w) + 0.5f * (d.w + e.w));
    }
    out4[i] = r;
}

// fused transpose + tf32 round for 4 weights: WT[z][n][k] = rna(W_z[k][n])
__global__ void transpose_rna4(const float* __restrict__ W0, const float* __restrict__ W1,
                               const float* __restrict__ W2, const float* __restrict__ W3,
                               float* __restrict__ WT) {
    __shared__ float tile[32][33];
    int z  = blockIdx.z;
    const float* W = (z == 0) ? W0 : (z == 1) ? W1 : (z == 2) ? W2 : W3;
    float* WTo = WT + (size_t)z * DIMC * DIMC;
    int k0 = blockIdx.x * 32, n0 = blockIdx.y * 32;
    int tx = threadIdx.x, ty = threadIdx.y;   // 32 x 8
#pragma unroll
    for (int i = ty; i < 32; i += 8)
        tile[i][tx] = rna_tf32(W[(size_t)(k0 + i) * DIMC + n0 + tx]);
    __syncthreads();
#pragma unroll
    for (int i = ty; i < 32; i += 8)
        WTo[(size_t)(n0 + i) * DIMC + k0 + tx] = tile[tx][i];
}

// ---------------------------------------------------------------------------
// attention: one warp per (b,t,h); lane = RoPE pair (lane, lane+32).
__global__ __launch_bounds__(256) void attn_kernel(
    const float* __restrict__ q, const float* __restrict__ offr,
    const float* __restrict__ kall, const float* __restrict__ vall,
    float* __restrict__ out) {
    int warp = (blockIdx.x * blockDim.x + threadIdx.x) >> 5;
    int lane = threadIdx.x & 31;
    int h = warp % HH;
    int t = (warp / HH) % TT;
    int b = warp / (HH * TT);
    if (b >= BB) return;

    const float LOG1E4 = 9.210340371976184f;
    float inv_freq = __expf(-(float)lane * (LOG1E4 / 32.0f));

    size_t qbase = ((size_t)(b * TT + t) * DIMC) + h * DHH + lane;
    float q1 = q[qbase], q2 = q[qbase + 32];
    float sq, cq;
    sincosf((float)t * inv_freq, &sq, &cq);
    float q1r = q1 * cq - q2 * sq;
    float q2r = q1 * sq + q2 * cq;

    float refp = (float)t * (1.0f / (float)(TT - 1));

    float p[LL * KKS];
    float vs1[LL * KKS], vs2[LL * KKS];

    const int TsA[3]     = {2048, 1024, 512};
    const int rowbase[3] = {0, 4096, 6144};
    int offb = ((b * TT + t) * HH + h) * (LL * KKS);

    float idxA[LL * KKS], w1A[LL * KKS];
    int   o0A[LL * KKS], o1A[LL * KKS];
#pragma unroll
    for (int l = 0; l < LL; l++) {
        int Ts = TsA[l];
        float Tm1 = (float)(Ts - 1);
        int lvb = (rowbase[l] + b * Ts) * DIMC + h * DHH + lane;
#pragma unroll
        for (int k = 0; k < KKS; k++) {
            int li = l * KKS + k;
            float ofv = tanhf(offr[offb + li]) * 0.25f;
            float s = fminf(fmaxf(refp + ofv, 0.f), 1.f);
            float idx = fminf(s * Tm1, Tm1 - 1e-6f);
            int i0 = (int)idx;
            int i1 = min(i0 + 1, Ts - 1);
            idxA[li] = idx;
            w1A[li]  = idx - (float)i0;
            o0A[li]  = lvb + i0 * DIMC;
            o1A[li]  = lvb + i1 * DIMC;
        }
    }

#pragma unroll
    for (int li = 0; li < LL * KKS; li++) {
        float w1 = w1A[li], w0 = 1.f - w1;
        const float* k0p = kall + o0A[li];
        const float* k1p = kall + o1A[li];
        const float* v0p = vall + o0A[li];
        const float* v1p = vall + o1A[li];
        float k0a = k0p[0],  k1a = k1p[0];
        float k0b = k0p[32], k1b = k1p[32];
        float v0a = v0p[0],  v1a = v1p[0];
        float v0b = v0p[32], v1b = v1p[32];

        float ks1 = w0 * k0a + w1 * k1a;
        float ks2 = w0 * k0b + w1 * k1b;
        vs1[li]   = w0 * v0a + w1 * v1a;
        vs2[li]   = w0 * v0b + w1 * v1b;

        float si, co;
        __sincosf(idxA[li] * inv_freq, &si, &co);
        float kr1 = ks1 * co - ks2 * si;
        float kr2 = ks1 * si + ks2 * co;
        p[li] = q1r * kr1 + q2r * kr2;
    }

#pragma unroll
    for (int d = 16; d > 0; d >>= 1) {
#pragma unroll
        for (int li = 0; li < LL * KKS; li++)
            p[li] += __shfl_xor_sync(0xffffffffu, p[li], d);
    }

    float m = p[0] * 0.125f;
#pragma unroll
    for (int i = 1; i < LL * KKS; i++) m = fmaxf(m, p[i] * 0.125f);
    float den = 0.f;
#pragma unroll
    for (int i = 0; i < LL * KKS; i++) {
        p[i] = __expf(p[i] * 0.125f - m);
        den += p[i];
    }
    float rden = 1.f / den;
    float o1 = 0.f, o2 = 0.f;
#pragma unroll
    for (int i = 0; i < LL * KKS; i++) {
        float a = p[i] * rden;
        o1 += a * vs1[i];
        o2 += a * vs2[i];
    }
    out[qbase]      = o1;
    out[qbase + 32] = o2;
}

// ---------------------------------------------------------------------------
extern "C" void kernel_launch(void* const* d_in, const int* in_sizes, int n_in,
                              void* d_out, int out_size) {
    const float* x    = (const float*)d_in[0];
    const float* Wq   = (const float*)d_in[2];
    const float* bq   = (const float*)d_in[3];
    const float* Wk   = (const float*)d_in[4];
    const float* bk   = (const float*)d_in[5];
    const float* Wv   = (const float*)d_in[6];
    const float* bv   = (const float*)d_in[7];
    const float* Woff = (const float*)d_in[8];
    const float* boff = (const float*)d_in[9];
    const float* Wo   = (const float*)d_in[10];
    const float* bo   = (const float*)d_in[11];
    float* out = (float*)d_out;

    float *qg, *offg, *kg, *vg, *aog, *wT;
    cudaGetSymbolAddress((void**)&qg,   g_q);
    cudaGetSymbolAddress((void**)&offg, g_off);
    cudaGetSymbolAddress((void**)&kg,   g_k);
    cudaGetSymbolAddress((void**)&vg,   g_v);
    cudaGetSymbolAddress((void**)&aog,  g_ao);
    cudaGetSymbolAddress((void**)&wT,   g_WqkvoT);

    cudaFuncSetAttribute(gemm_tf32, cudaFuncAttributeMaxDynamicSharedMemorySize,
                         GEMM_SMEM);

    // side stream + events for capture-legal fork/join (resources only)
    static cudaStream_t s_side = nullptr;
    static cudaEvent_t e_fork = nullptr, e_join = nullptr;
    if (s_side == nullptr) {
        cudaStreamCreateWithFlags(&s_side, cudaStreamNonBlocking);
        cudaEventCreateWithFlags(&e_fork, cudaEventDisableTiming);
        cudaEventCreateWithFlags(&e_join, cudaEventDisableTiming);
    }

    // fork: offset projection (exact fp32, depends only on x, feeds only attn)
    cudaEventRecord(e_fork, 0);
    cudaStreamWaitEvent(s_side, e_fork, 0);
    {
        dim3 grid(2, (BB * TT) / 128);
        sgemm_bias<<<grid, 256, 0, s_side>>>(BB * TT, HH * LL * KKS, DIMC,
                                             x, Woff, boff, offg);
        cudaEventRecord(e_join, s_side);
    }

    // main stream: transpose+round weights
    transpose_rna4<<<dim3(32, 32, 4), dim3(32, 8)>>>(Wq, Wk, Wv, Wo, wT);

    // fused Q/K/V level-0 projection: x @ [Wq|Wk|Wv] (N=3072)
    gemm_tf32<<<dim3(24, 32), 128, GEMM_SMEM>>>(
        x, wT, bq, bk, bv, qg, kg, vg);

    // K/V pyramid levels (both from level 0; one launch)
    {
        int n1 = BB * 1024 * (DIMC / 4);
        int blocks = (n1 + 255) / 256;
        downsample_all<<<dim3(blocks, 1, 4), 256>>>(
            kg, vg,
            kg + (size_t)4096 * DIMC, vg + (size_t)4096 * DIMC,
            kg + (size_t)6144 * DIMC, vg + (size_t)6144 * DIMC);
    }

    // join: attention needs the offsets from the side stream
    cudaStreamWaitEvent(0, e_join, 0);

    // deformable attention
    {
        int warps = BB * TT * HH;
        attn_kernel<<<warps / 8, 256>>>(qg, offg, kg, vg, aog);
    }

    // output projection -> d_out  (Wo is segment 3 of wT)
    gemm_tf32<<<dim3(8, 32), 128, GEMM_SMEM>>>(
        aog, wT + (size_t)3 * DIMC * DIMC, bo, bo, bo, out, out, out);
}

// round 14
// speedup vs baseline: 1.4632x; 1.0520x over previous
#include <cuda_runtime.h>
#include <math.h>
#include <stdint.h>

// ---------------------------------------------------------------------------
// Problem constants (fixed by setup_inputs)
#define BB   2
#define TT   2048
#define DIMC 1024
#define HH   16
#define DHH  64
#define LL   3
#define KKS  4
#define TOTROWS 7168           // 4096 + 2048 + 1024 rows of K/V

// GEMM tiling: 128x128 CTA tile, BK=32, 3-stage cp.async, 4 warps (64x64 each)
#define BM 128
#define BN 128
#define BK 32
#define NSTAGE 3
#define NT (DIMC / BK)          // 32 k-iterations
#define ROWF 36                 // smem row stride in floats (144B)
#define TILEF (BM * ROWF)
#define STAGEF (2 * TILEF)
#define GEMM_SMEM (NSTAGE * STAGEF * 4)   // 110592 bytes -> 2 CTAs/SM

// ---------------------------------------------------------------------------
// scratch (device globals; no allocation allowed)
__device__ float g_q     [BB * TT * DIMC];
__device__ float g_off   [BB * TT * HH * LL * KKS];
__device__ float g_k     [TOTROWS * DIMC];
__device__ float g_v     [TOTROWS * DIMC];
__device__ float g_ao    [BB * TT * DIMC];
__device__ float g_WqkvoT[4 * DIMC * DIMC];          // [Wq;Wk;Wv;Wo] transposed [N,K]

// ---------------------------------------------------------------------------
__device__ __forceinline__ float rna_tf32(float x) {
    float r;
    asm("cvt.rna.tf32.f32 %0, %1;" : "=f"(r) : "f"(x));
    return r;
}
__device__ __forceinline__ uint32_t rna_tf32_u(uint32_t x) {
    uint32_t r;
    asm("cvt.rna.tf32.f32 %0, %1;" : "=r"(r) : "r"(x));
    return r;
}
__device__ __forceinline__ uint32_t smem_u32(const void* p) {
    uint32_t a;
    asm("{ .reg .u64 t; cvta.to.shared.u64 t, %1; cvt.u32.u64 %0, t; }"
        : "=r"(a) : "l"(p));
    return a;
}
__device__ __forceinline__ void cp_async16(uint32_t dst, const void* src) {
    asm volatile("cp.async.cg.shared.global [%0], [%1], 16;"
                 :: "r"(dst), "l"(src) : "memory");
}
__device__ __forceinline__ void cp_commit() {
    asm volatile("cp.async.commit_group;" ::: "memory");
}
template <int N>
__device__ __forceinline__ void cp_wait() {
    asm volatile("cp.async.wait_group %0;" :: "n"(N) : "memory");
}
__device__ __forceinline__ void ldsm_x4(uint32_t& r0, uint32_t& r1,
                                        uint32_t& r2, uint32_t& r3, uint32_t addr) {
    asm volatile("ldmatrix.sync.aligned.m8n8.x4.shared.b16 {%0,%1,%2,%3}, [%4];"
                 : "=r"(r0), "=r"(r1), "=r"(r2), "=r"(r3) : "r"(addr));
}
__device__ __forceinline__ void mma_tf32(float& d0, float& d1, float& d2, float& d3,
                                         uint32_t a0, uint32_t a1, uint32_t a2, uint32_t a3,
                                         uint32_t b0, uint32_t b1) {
    asm volatile(
        "mma.sync.aligned.m16n8k8.row.col.f32.tf32.tf32.f32 "
        "{%0,%1,%2,%3}, {%4,%5,%6,%7}, {%8,%9}, {%0,%1,%2,%3};"
        : "+f"(d0), "+f"(d1), "+f"(d2), "+f"(d3)
        : "r"(a0), "r"(a1), "r"(a2), "r"(a3), "r"(b0), "r"(b1));
}

// ---------------------------------------------------------------------------
// tf32 mma.sync GEMM, 128x128 tile, 4 warps (2x2, 64x64 warp tiles),
// ldmatrix + in-register RN rounding of A, segmented output routing.
__global__ __launch_bounds__(128, 2) void gemm_tf32(
    const float* __restrict__ A, const float* __restrict__ BT,
    const float* __restrict__ b0, const float* __restrict__ b1,
    const float* __restrict__ b2,
    float* __restrict__ C0, float* __restrict__ C1, float* __restrict__ C2) {
    extern __shared__ float smem[];

    int tid  = threadIdx.x;
    int wid  = tid >> 5, lane = tid & 31;
    int gid  = lane >> 2, tg = lane & 3;
    int wm   = wid >> 1;
    int wn   = wid & 1;
    int m0   = blockIdx.y * BM;

    int seg  = blockIdx.x >> 3;
    int ncol = (blockIdx.x & 7) * BN;
    const float* bias = (seg == 0) ? b0 : (seg == 1) ? b1 : b2;
    float* C          = (seg == 0) ? C0 : (seg == 1) ? C1 : C2;

    uint32_t sbase = smem_u32(smem);

    const float* Abase = A  + (size_t)m0 * DIMC;
    const float* Bbase = BT + (size_t)blockIdx.x * BN * DIMC;

    int lrow = lane & 7;
    int lm8  = (lane >> 3) & 1;
    int lk4  = (lane >> 4) & 1;
    uint32_t a_off[4];
#pragma unroll
    for (int mi = 0; mi < 4; mi++) {
        int row = wm * 64 + mi * 16 + lm8 * 8 + lrow;
        a_off[mi] = (uint32_t)((row * ROWF + lk4 * 4) * 4);
    }
    uint32_t bt_off[4];
#pragma unroll
    for (int p = 0; p < 4; p++) {
        int n = wn * 64 + p * 16 + lk4 * 8 + lrow;
        bt_off[p] = (uint32_t)((n * ROWF + lm8 * 4) * 4);
    }

    float acc[4][8][4];
#pragma unroll
    for (int mi = 0; mi < 4; mi++)
#pragma unroll
        for (int ni = 0; ni < 8; ni++)
#pragma unroll
            for (int r = 0; r < 4; r++) acc[mi][ni][r] = 0.f;

#define ISSUE_STAGE(pt) do {                                                   \
        uint32_t sa_  = sbase + (((pt) % NSTAGE) * STAGEF) * 4;                \
        uint32_t sbB_ = sa_ + TILEF * 4;                                       \
        _Pragma("unroll")                                                      \
        for (int i_ = 0; i_ < 8; i_++) {                                       \
            int cid_ = i_ * 128 + tid;                                         \
            int r_ = cid_ >> 3, c_ = cid_ & 7;                                 \
            cp_async16(sa_ + (r_ * ROWF + c_ * 4) * 4,                         \
                       Abase + (size_t)r_ * DIMC + (pt) * BK + c_ * 4);        \
            cp_async16(sbB_ + (r_ * ROWF + c_ * 4) * 4,                        \
                       Bbase + (size_t)r_ * DIMC + (pt) * BK + c_ * 4);        \
        }                                                                      \
        cp_commit();                                                           \
    } while (0)

    ISSUE_STAGE(0);
    ISSUE_STAGE(1);

    for (int kt = 0; kt < NT; kt++) {
        if (kt + 2 < NT) cp_wait<1>(); else cp_wait<0>();
        __syncthreads();

        if (kt + 2 < NT) ISSUE_STAGE(kt + 2);

        uint32_t abase = sbase + ((kt % NSTAGE) * STAGEF) * 4;
        uint32_t bbase = abase + TILEF * 4;

#pragma unroll
        for (int j = 0; j < 4; j++) {
            uint32_t af[4][4], bf[8][2];
            uint32_t jb = (uint32_t)(j * 32);
#pragma unroll
            for (int mi = 0; mi < 4; mi++) {
                ldsm_x4(af[mi][0], af[mi][1], af[mi][2], af[mi][3],
                        abase + a_off[mi] + jb);
                af[mi][0] = rna_tf32_u(af[mi][0]);
                af[mi][1] = rna_tf32_u(af[mi][1]);
                af[mi][2] = rna_tf32_u(af[mi][2]);
                af[mi][3] = rna_tf32_u(af[mi][3]);
            }
#pragma unroll
            for (int p = 0; p < 4; p++)
                ldsm_x4(bf[2 * p][0], bf[2 * p][1], bf[2 * p + 1][0],
                        bf[2 * p + 1][1], bbase + bt_off[p] + jb);
#pragma unroll
            for (int mi = 0; mi < 4; mi++)
#pragma unroll
                for (int ni = 0; ni < 8; ni++)
                    mma_tf32(acc[mi][ni][0], acc[mi][ni][1],
                             acc[mi][ni][2], acc[mi][ni][3],
                             af[mi][0], af[mi][1], af[mi][2], af[mi][3],
                             bf[ni][0], bf[ni][1]);
        }
    }

#pragma unroll
    for (int mi = 0; mi < 4; mi++) {
        int r0 = m0 + wm * 64 + mi * 16 + gid;
#pragma unroll
        for (int ni = 0; ni < 8; ni++) {
            int c = ncol + wn * 64 + ni * 8 + tg * 2;
            float bx = bias[c], by = bias[c + 1];
            float2 o0 = make_float2(acc[mi][ni][0] + bx, acc[mi][ni][1] + by);
            float2 o1 = make_float2(acc[mi][ni][2] + bx, acc[mi][ni][3] + by);
            *(float2*)&C[(size_t)r0 * DIMC + c] = o0;
            *(float2*)&C[(size_t)(r0 + 8) * DIMC + c] = o1;
        }
    }
#undef ISSUE_STAGE
}

// ---------------------------------------------------------------------------
// fp32 SGEMM (exact) for the offset projection: C[M,N] = A@W + bias, N=192
__global__ __launch_bounds__(256) void sgemm_bias(
    int M, int N, int K,
    const float* __restrict__ A, const float* __restrict__ W,
    const float* __restrict__ bias, float* __restrict__ C) {
    __shared__ float As[8][128];
    __shared__ float Bs[8][128];

    int tid = threadIdx.x;
    int bm = blockIdx.y, bn = blockIdx.x;

    int aRow = tid >> 1;
    int aCol = (tid & 1) * 4;
    int bRow = tid >> 5;
    int bCol = (tid & 31) * 4;
    int wcol = bn * 128 + bCol;

    int tRow = (tid >> 4) * 8;
    int tCol = (tid & 15) * 8;

    const float* Ab = A + (size_t)(bm * 128 + aRow) * K + aCol;

    float acc[8][8];
#pragma unroll
    for (int i = 0; i < 8; i++)
#pragma unroll
        for (int j = 0; j < 8; j++) acc[i][j] = 0.f;

    for (int k0 = 0; k0 < K; k0 += 8) {
        float4 av = *(const float4*)(Ab + k0);
        As[aCol + 0][aRow] = av.x;
        As[aCol + 1][aRow] = av.y;
        As[aCol + 2][aRow] = av.z;
        As[aCol + 3][aRow] = av.w;
        float4 wv = make_float4(0.f, 0.f, 0.f, 0.f);
        if (wcol < N)
            wv = *(const float4*)(W + (size_t)(k0 + bRow) * N + wcol);
        *(float4*)&Bs[bRow][bCol] = wv;
        __syncthreads();
#pragma unroll
        for (int kk = 0; kk < 8; kk++) {
            float4 a0 = *(const float4*)&As[kk][tRow];
            float4 a1 = *(const float4*)&As[kk][tRow + 4];
            float4 b0 = *(const float4*)&Bs[kk][tCol];
            float4 b1 = *(const float4*)&Bs[kk][tCol + 4];
            float av8[8] = {a0.x, a0.y, a0.z, a0.w, a1.x, a1.y, a1.z, a1.w};
            float bv8[8] = {b0.x, b0.y, b0.z, b0.w, b1.x, b1.y, b1.z, b1.w};
#pragma unroll
            for (int i = 0; i < 8; i++)
#pragma unroll
                for (int j = 0; j < 8; j++) acc[i][j] += av8[i] * bv8[j];
        }
        __syncthreads();
    }

#pragma unroll
    for (int i = 0; i < 8; i++) {
        size_t row = (size_t)(bm * 128 + tRow + i);
#pragma unroll
        for (int j = 0; j < 8; j += 4) {
            int col = bn * 128 + tCol + j;
            if (col < N) {
                float4 o;
                o.x = acc[i][j + 0] + bias[col + 0];
                o.y = acc[i][j + 1] + bias[col + 1];
                o.z = acc[i][j + 2] + bias[col + 2];
                o.w = acc[i][j + 3] + bias[col + 3];
                *(float4*)&C[row * N + col] = o;
            }
        }
    }
}

// ---------------------------------------------------------------------------
// per-batch K/V pyramid: pointers are batch-offset; 4 jobs via blockIdx.z.
//   z=0: K level1   z=1: V level1   z=2: K level2 (4-row)   z=3: V level2
__global__ void downsample_b(const float* __restrict__ k0,
                             const float* __restrict__ v0,
                             float* __restrict__ k1, float* __restrict__ v1,
                             float* __restrict__ k2, float* __restrict__ v2) {
    int z = blockIdx.z;
    int lvl2 = z >> 1;
    int Tout = lvl2 ? 512 : 1024;
    int n = Tout * (DIMC / 4);
    int i = blockIdx.x * blockDim.x + threadIdx.x;
    if (i >= n) return;
    int c4 = i % (DIMC / 4);
    int t  = i / (DIMC / 4);
    const float4* in4 = (const float4*)((z & 1) ? v0 : k0);
    float4* out4 = (float4*)(lvl2 ? ((z & 1) ? v2 : k2) : ((z & 1) ? v1 : k1));
    int t0 = t << (1 + lvl2);
    float4 a = in4[(size_t)t0       * (DIMC / 4) + c4];
    float4 c = in4[(size_t)(t0 + 1) * (DIMC / 4) + c4];
    float4 r;
    if (!lvl2) {
        r.x = 0.5f * (a.x + c.x);
        r.y = 0.5f * (a.y + c.y);
        r.z = 0.5f * (a.z + c.z);
        r.w = 0.5f * (a.w + c.w);
    } else {
        float4 d = in4[(size_t)(t0 + 2) * (DIMC / 4) + c4];
        float4 e = in4[(size_t)(t0 + 3) * (DIMC / 4) + c4];
        r.x = 0.5f * (0.5f * (a.x + c.x) + 0.5f * (d.x + e.x));
        r.y = 0.5f * (0.5f * (a.y + c.y) + 0.5f * (d.y + e.y));
        r.z = 0.5f * (0.5f * (a.z + c.z) + 0.5f * (d.z + e.z));
        r.w = 0.5f * (0.5f * (a.w + c.w) + 0.5f * (d.w + e.w));
    }
    out4[i] = r;
}

// fused transpose + tf32 round for 4 weights: WT[z][n][k] = rna(W_z[k][n])
__global__ void transpose_rna4(const float* __restrict__ W0, const float* __restrict__ W1,
                               const float* __restrict__ W2, const float* __restrict__ W3,
                               float* __restrict__ WT) {
    __shared__ float tile[32][33];
    int z  = blockIdx.z;
    const float* W = (z == 0) ? W0 : (z == 1) ? W1 : (z == 2) ? W2 : W3;
    float* WTo = WT + (size_t)z * DIMC * DIMC;
    int k0 = blockIdx.x * 32, n0 = blockIdx.y * 32;
    int tx = threadIdx.x, ty = threadIdx.y;   // 32 x 8
#pragma unroll
    for (int i = ty; i < 32; i += 8)
        tile[i][tx] = rna_tf32(W[(size_t)(k0 + i) * DIMC + n0 + tx]);
    __syncthreads();
#pragma unroll
    for (int i = ty; i < 32; i += 8)
        WTo[(size_t)(n0 + i) * DIMC + k0 + tx] = tile[tx][i];
}

// ---------------------------------------------------------------------------
// attention for one batch (b fixed): one warp per (t,h).
__global__ __launch_bounds__(256) void attn_kernel(
    const float* __restrict__ q, const float* __restrict__ offr,
    const float* __restrict__ kall, const float* __restrict__ vall,
    float* __restrict__ out, int b) {
    int warp = (blockIdx.x * blockDim.x + threadIdx.x) >> 5;
    int lane = threadIdx.x & 31;
    int h = warp % HH;
    int t = warp / HH;
    if (t >= TT) return;

    const float LOG1E4 = 9.210340371976184f;
    float inv_freq = __expf(-(float)lane * (LOG1E4 / 32.0f));

    size_t qbase = ((size_t)(b * TT + t) * DIMC) + h * DHH + lane;
    float q1 = q[qbase], q2 = q[qbase + 32];
    float sq, cq;
    sincosf((float)t * inv_freq, &sq, &cq);
    float q1r = q1 * cq - q2 * sq;
    float q2r = q1 * sq + q2 * cq;

    float refp = (float)t * (1.0f / (float)(TT - 1));

    float p[LL * KKS];
    float vs1[LL * KKS], vs2[LL * KKS];

    const int TsA[3]     = {2048, 1024, 512};
    const int rowbase[3] = {0, 4096, 6144};
    int offb = ((b * TT + t) * HH + h) * (LL * KKS);

    float idxA[LL * KKS], w1A[LL * KKS];
    int   o0A[LL * KKS], o1A[LL * KKS];
#pragma unroll
    for (int l = 0; l < LL; l++) {
        int Ts = TsA[l];
        float Tm1 = (float)(Ts - 1);
        int lvb = (rowbase[l] + b * Ts) * DIMC + h * DHH + lane;
#pragma unroll
        for (int k = 0; k < KKS; k++) {
            int li = l * KKS + k;
            float ofv = tanhf(offr[offb + li]) * 0.25f;
            float s = fminf(fmaxf(refp + ofv, 0.f), 1.f);
            float idx = fminf(s * Tm1, Tm1 - 1e-6f);
            int i0 = (int)idx;
            int i1 = min(i0 + 1, Ts - 1);
            idxA[li] = idx;
            w1A[li]  = idx - (float)i0;
            o0A[li]  = lvb + i0 * DIMC;
            o1A[li]  = lvb + i1 * DIMC;
        }
    }

#pragma unroll
    for (int li = 0; li < LL * KKS; li++) {
        float w1 = w1A[li], w0 = 1.f - w1;
        const float* k0p = kall + o0A[li];
        const float* k1p = kall + o1A[li];
        const float* v0p = vall + o0A[li];
        const float* v1p = vall + o1A[li];
        float k0a = k0p[0],  k1a = k1p[0];
        float k0b = k0p[32], k1b = k1p[32];
        float v0a = v0p[0],  v1a = v1p[0];
        float v0b = v0p[32], v1b = v1p[32];

        float ks1 = w0 * k0a + w1 * k1a;
        float ks2 = w0 * k0b + w1 * k1b;
        vs1[li]   = w0 * v0a + w1 * v1a;
        vs2[li]   = w0 * v0b + w1 * v1b;

        float si, co;
        __sincosf(idxA[li] * inv_freq, &si, &co);
        float kr1 = ks1 * co - ks2 * si;
        float kr2 = ks1 * si + ks2 * co;
        p[li] = q1r * kr1 + q2r * kr2;
    }

#pragma unroll
    for (int d = 16; d > 0; d >>= 1) {
#pragma unroll
        for (int li = 0; li < LL * KKS; li++)
            p[li] += __shfl_xor_sync(0xffffffffu, p[li], d);
    }

    float m = p[0] * 0.125f;
#pragma unroll
    for (int i = 1; i < LL * KKS; i++) m = fmaxf(m, p[i] * 0.125f);
    float den = 0.f;
#pragma unroll
    for (int i = 0; i < LL * KKS; i++) {
        p[i] = __expf(p[i] * 0.125f - m);
        den += p[i];
    }
    float rden = 1.f / den;
    float o1 = 0.f, o2 = 0.f;
#pragma unroll
    for (int i = 0; i < LL * KKS; i++) {
        float a = p[i] * rden;
        o1 += a * vs1[i];
        o2 += a * vs2[i];
    }
    out[qbase]      = o1;
    out[qbase + 32] = o2;
}

// ---------------------------------------------------------------------------
extern "C" void kernel_launch(void* const* d_in, const int* in_sizes, int n_in,
                              void* d_out, int out_size) {
    const float* x    = (const float*)d_in[0];
    const float* Wq   = (const float*)d_in[2];
    const float* bq   = (const float*)d_in[3];
    const float* Wk   = (const float*)d_in[4];
    const float* bk   = (const float*)d_in[5];
    const float* Wv   = (const float*)d_in[6];
    const float* bv   = (const float*)d_in[7];
    const float* Woff = (const float*)d_in[8];
    const float* boff = (const float*)d_in[9];
    const float* Wo   = (const float*)d_in[10];
    const float* bo   = (const float*)d_in[11];
    float* out = (float*)d_out;

    float *qg, *offg, *kg, *vg, *aog, *wT;
    cudaGetSymbolAddress((void**)&qg,   g_q);
    cudaGetSymbolAddress((void**)&offg, g_off);
    cudaGetSymbolAddress((void**)&kg,   g_k);
    cudaGetSymbolAddress((void**)&vg,   g_v);
    cudaGetSymbolAddress((void**)&aog,  g_ao);
    cudaGetSymbolAddress((void**)&wT,   g_WqkvoT);

    cudaFuncSetAttribute(gemm_tf32, cudaFuncAttributeMaxDynamicSharedMemorySize,
                         GEMM_SMEM);

    // streams + events for capture-legal fork/join (resources only)
    static cudaStream_t s_b1 = nullptr, s_off = nullptr;
    static cudaEvent_t e_fork = nullptr, e_off = nullptr, e_w = nullptr,
                       e_b1 = nullptr;
    if (s_b1 == nullptr) {
        cudaStreamCreateWithFlags(&s_b1, cudaStreamNonBlocking);
        cudaStreamCreateWithFlags(&s_off, cudaStreamNonBlocking);
        cudaEventCreateWithFlags(&e_fork, cudaEventDisableTiming);
        cudaEventCreateWithFlags(&e_off, cudaEventDisableTiming);
        cudaEventCreateWithFlags(&e_w, cudaEventDisableTiming);
        cudaEventCreateWithFlags(&e_b1, cudaEventDisableTiming);
    }

    // fork point
    cudaEventRecord(e_fork, 0);
    cudaStreamWaitEvent(s_off, e_fork, 0);
    cudaStreamWaitEvent(s_b1, e_fork, 0);

    // offset stream: exact fp32 projection for BOTH batches
    {
        dim3 grid(2, (BB * TT) / 128);
        sgemm_bias<<<grid, 256, 0, s_off>>>(BB * TT, HH * LL * KKS, DIMC,
                                            x, Woff, boff, offg);
        cudaEventRecord(e_off, s_off);
    }

    // main (b0) stream: weights first
    transpose_rna4<<<dim3(32, 32, 4), dim3(32, 8)>>>(Wq, Wk, Wv, Wo, wT);
    cudaEventRecord(e_w, 0);
    cudaStreamWaitEvent(s_b1, e_w, 0);   // b1 chain needs weights

    const size_t bstride = (size_t)TT * DIMC;   // 2048*1024 floats per batch
    // per-batch chains
    for (int b = 0; b < 2; b++) {
        cudaStream_t st = (b == 0) ? (cudaStream_t)0 : s_b1;
        const float* xb = x + b * bstride;
        float* qb = qg + b * bstride;
        float* kb = kg + b * bstride;
        float* vb = vg + b * bstride;
        float* ab = aog + b * bstride;
        float* ob = out + b * bstride;

        // QKV projection for this batch (M=2048)
        gemm_tf32<<<dim3(24, 16), 128, GEMM_SMEM, st>>>(
            xb, wT, bq, bk, bv, qb, kb, vb);

        // pyramid for this batch
        {
            float* k1 = kg + ((size_t)4096 + b * 1024) * DIMC;
            float* v1 = vg + ((size_t)4096 + b * 1024) * DIMC;
            float* k2 = kg + ((size_t)6144 + b * 512) * DIMC;
            float* v2 = vg + ((size_t)6144 + b * 512) * DIMC;
            int blocks = (1024 * (DIMC / 4) + 255) / 256;
            downsample_b<<<dim3(blocks, 1, 4), 256, 0, st>>>(
                kb, vb, k1, v1, k2, v2);
        }

        // attention needs offsets
        cudaStreamWaitEvent(st, e_off, 0);
        {
            int warps = TT * HH;          // 32768 per batch
            attn_kernel<<<warps / 8, 256, 0, st>>>(qg, offg, kg, vg, aog, b);
        }

        // output projection for this batch
        gemm_tf32<<<dim3(8, 16), 128, GEMM_SMEM, st>>>(
            ab, wT + (size_t)3 * DIMC * DIMC, bo, bo, bo, ob, ob, ob);
    }

    // join b1 into the main stream
    cudaEventRecord(e_b1, s_b1);
    cudaStreamWaitEvent(0, e_b1, 0);
}

// round 15
// speedup vs baseline: 1.5026x; 1.0269x over previous
#include <cuda_runtime.h>
#include <math.h>
#include <stdint.h>

// ---------------------------------------------------------------------------
// Problem constants (fixed by setup_inputs)
#define BB   2
#define TT   2048
#define DIMC 1024
#define HH   16
#define DHH  64
#define LL   3
#define KKS  4
#define TOTROWS 7168           // 4096 + 2048 + 1024 rows of K/V

// GEMM tiling: 128x128 CTA tile, BK=32, 3-stage cp.async, 4 warps (64x64 each)
#define BM 128
#define BN 128
#define BK 32
#define NSTAGE 3
#define NT (DIMC / BK)          // 32 k-iterations
#define ROWF 36                 // smem row stride in floats (144B)
#define TILEF (BM * ROWF)
#define STAGEF (2 * TILEF)
#define GEMM_SMEM (NSTAGE * STAGEF * 4)   // 110592 bytes -> 2 CTAs/SM

// Head-dim interleave permutation: old col d = h*64 + s*32 + j  (s in {0,1})
//   -> new position h*64 + 2*j + s.  RoPE pair (j, j+32) becomes adjacent.
#define PERM(d) (((d) & ~63) | ((((d) & 31) << 1) | (((d) >> 5) & 1)))

// ---------------------------------------------------------------------------
// scratch (device globals; no allocation allowed)
__device__ float g_q     [BB * TT * DIMC];
__device__ float g_off   [BB * TT * HH * LL * KKS];
__device__ float g_k     [TOTROWS * DIMC];
__device__ float g_v     [TOTROWS * DIMC];
__device__ float g_ao    [BB * TT * DIMC];
__device__ float g_WqkvoT[4 * DIMC * DIMC];          // [Wq;Wk;Wv;Wo] transposed [N,K]

// ---------------------------------------------------------------------------
__device__ __forceinline__ float rna_tf32(float x) {
    float r;
    asm("cvt.rna.tf32.f32 %0, %1;" : "=f"(r) : "f"(x));
    return r;
}
__device__ __forceinline__ uint32_t rna_tf32_u(uint32_t x) {
    uint32_t r;
    asm("cvt.rna.tf32.f32 %0, %1;" : "=r"(r) : "r"(x));
    return r;
}
__device__ __forceinline__ uint32_t smem_u32(const void* p) {
    uint32_t a;
    asm("{ .reg .u64 t; cvta.to.shared.u64 t, %1; cvt.u32.u64 %0, t; }"
        : "=r"(a) : "l"(p));
    return a;
}
__device__ __forceinline__ void cp_async16(uint32_t dst, const void* src) {
    asm volatile("cp.async.cg.shared.global [%0], [%1], 16;"
                 :: "r"(dst), "l"(src) : "memory");
}
__device__ __forceinline__ void cp_commit() {
    asm volatile("cp.async.commit_group;" ::: "memory");
}
template <int N>
__device__ __forceinline__ void cp_wait() {
    asm volatile("cp.async.wait_group %0;" :: "n"(N) : "memory");
}
__device__ __forceinline__ void ldsm_x4(uint32_t& r0, uint32_t& r1,
                                        uint32_t& r2, uint32_t& r3, uint32_t addr) {
    asm volatile("ldmatrix.sync.aligned.m8n8.x4.shared.b16 {%0,%1,%2,%3}, [%4];"
                 : "=r"(r0), "=r"(r1), "=r"(r2), "=r"(r3) : "r"(addr));
}
__device__ __forceinline__ void mma_tf32(float& d0, float& d1, float& d2, float& d3,
                                         uint32_t a0, uint32_t a1, uint32_t a2, uint32_t a3,
                                         uint32_t b0, uint32_t b1) {
    asm volatile(
        "mma.sync.aligned.m16n8k8.row.col.f32.tf32.tf32.f32 "
        "{%0,%1,%2,%3}, {%4,%5,%6,%7}, {%8,%9}, {%0,%1,%2,%3};"
        : "+f"(d0), "+f"(d1), "+f"(d2), "+f"(d3)
        : "r"(a0), "r"(a1), "r"(a2), "r"(a3), "r"(b0), "r"(b1));
}

// ---------------------------------------------------------------------------
// tf32 mma.sync GEMM, 128x128 tile, 4 warps (2x2, 64x64 warp tiles),
// ldmatrix + in-register RN rounding of A, segmented output routing.
// permb: bias indexed through inverse head-interleave permutation.
__global__ __launch_bounds__(128, 2) void gemm_tf32(
    const float* __restrict__ A, const float* __restrict__ BT,
    const float* __restrict__ b0, const float* __restrict__ b1,
    const float* __restrict__ b2,
    float* __restrict__ C0, float* __restrict__ C1, float* __restrict__ C2,
    int permb) {
    extern __shared__ float smem[];

    int tid  = threadIdx.x;
    int wid  = tid >> 5, lane = tid & 31;
    int gid  = lane >> 2, tg = lane & 3;
    int wm   = wid >> 1;
    int wn   = wid & 1;
    int m0   = blockIdx.y * BM;

    int seg  = blockIdx.x >> 3;
    int ncol = (blockIdx.x & 7) * BN;
    const float* bias = (seg == 0) ? b0 : (seg == 1) ? b1 : b2;
    float* C          = (seg == 0) ? C0 : (seg == 1) ? C1 : C2;

    uint32_t sbase = smem_u32(smem);

    const float* Abase = A  + (size_t)m0 * DIMC;
    const float* Bbase = BT + (size_t)blockIdx.x * BN * DIMC;

    int lrow = lane & 7;
    int lm8  = (lane >> 3) & 1;
    int lk4  = (lane >> 4) & 1;
    uint32_t a_off[4];
#pragma unroll
    for (int mi = 0; mi < 4; mi++) {
        int row = wm * 64 + mi * 16 + lm8 * 8 + lrow;
        a_off[mi] = (uint32_t)((row * ROWF + lk4 * 4) * 4);
    }
    uint32_t bt_off[4];
#pragma unroll
    for (int p = 0; p < 4; p++) {
        int n = wn * 64 + p * 16 + lk4 * 8 + lrow;
        bt_off[p] = (uint32_t)((n * ROWF + lm8 * 4) * 4);
    }

    float acc[4][8][4];
#pragma unroll
    for (int mi = 0; mi < 4; mi++)
#pragma unroll
        for (int ni = 0; ni < 8; ni++)
#pragma unroll
            for (int r = 0; r < 4; r++) acc[mi][ni][r] = 0.f;

#define ISSUE_STAGE(pt) do {                                                   \
        uint32_t sa_  = sbase + (((pt) % NSTAGE) * STAGEF) * 4;                \
        uint32_t sbB_ = sa_ + TILEF * 4;                                       \
        _Pragma("unroll")                                                      \
        for (int i_ = 0; i_ < 8; i_++) {                                       \
            int cid_ = i_ * 128 + tid;                                         \
            int r_ = cid_ >> 3, c_ = cid_ & 7;                                 \
            cp_async16(sa_ + (r_ * ROWF + c_ * 4) * 4,                         \
                       Abase + (size_t)r_ * DIMC + (pt) * BK + c_ * 4);        \
            cp_async16(sbB_ + (r_ * ROWF + c_ * 4) * 4,                        \
                       Bbase + (size_t)r_ * DIMC + (pt) * BK + c_ * 4);        \
        }                                                                      \
        cp_commit();                                                           \
    } while (0)

    ISSUE_STAGE(0);
    ISSUE_STAGE(1);

    for (int kt = 0; kt < NT; kt++) {
        if (kt + 2 < NT) cp_wait<1>(); else cp_wait<0>();
        __syncthreads();

        if (kt + 2 < NT) ISSUE_STAGE(kt + 2);

        uint32_t abase = sbase + ((kt % NSTAGE) * STAGEF) * 4;
        uint32_t bbase = abase + TILEF * 4;

#pragma unroll
        for (int j = 0; j < 4; j++) {
            uint32_t af[4][4], bf[8][2];
            uint32_t jb = (uint32_t)(j * 32);
#pragma unroll
            for (int mi = 0; mi < 4; mi++) {
                ldsm_x4(af[mi][0], af[mi][1], af[mi][2], af[mi][3],
                        abase + a_off[mi] + jb);
                af[mi][0] = rna_tf32_u(af[mi][0]);
                af[mi][1] = rna_tf32_u(af[mi][1]);
                af[mi][2] = rna_tf32_u(af[mi][2]);
                af[mi][3] = rna_tf32_u(af[mi][3]);
            }
#pragma unroll
            for (int p = 0; p < 4; p++)
                ldsm_x4(bf[2 * p][0], bf[2 * p][1], bf[2 * p + 1][0],
                        bf[2 * p + 1][1], bbase + bt_off[p] + jb);
#pragma unroll
            for (int mi = 0; mi < 4; mi++)
#pragma unroll
                for (int ni = 0; ni < 8; ni++)
                    mma_tf32(acc[mi][ni][0], acc[mi][ni][1],
                             acc[mi][ni][2], acc[mi][ni][3],
                             af[mi][0], af[mi][1], af[mi][2], af[mi][3],
                             bf[ni][0], bf[ni][1]);
        }
    }

#pragma unroll
    for (int mi = 0; mi < 4; mi++) {
        int r0 = m0 + wm * 64 + mi * 16 + gid;
#pragma unroll
        for (int ni = 0; ni < 8; ni++) {
            int c = ncol + wn * 64 + ni * 8 + tg * 2;   // even
            float bx, by;
            if (permb) {
                int hbase = c & ~63;
                int jj = (c & 63) >> 1;
                bx = bias[hbase + jj];
                by = bias[hbase + 32 + jj];
            } else {
                bx = bias[c];
                by = bias[c + 1];
            }
            float2 o0 = make_float2(acc[mi][ni][0] + bx, acc[mi][ni][1] + by);
            float2 o1 = make_float2(acc[mi][ni][2] + bx, acc[mi][ni][3] + by);
            *(float2*)&C[(size_t)r0 * DIMC + c] = o0;
            *(float2*)&C[(size_t)(r0 + 8) * DIMC + c] = o1;
        }
    }
#undef ISSUE_STAGE
}

// ---------------------------------------------------------------------------
// fp32 SGEMM (exact) for the offset projection: C[M,N] = A@W + bias, N=192
__global__ __launch_bounds__(256) void sgemm_bias(
    int M, int N, int K,
    const float* __restrict__ A, const float* __restrict__ W,
    const float* __restrict__ bias, float* __restrict__ C) {
    __shared__ float As[8][128];
    __shared__ float Bs[8][128];

    int tid = threadIdx.x;
    int bm = blockIdx.y, bn = blockIdx.x;

    int aRow = tid >> 1;
    int aCol = (tid & 1) * 4;
    int bRow = tid >> 5;
    int bCol = (tid & 31) * 4;
    int wcol = bn * 128 + bCol;

    int tRow = (tid >> 4) * 8;
    int tCol = (tid & 15) * 8;

    const float* Ab = A + (size_t)(bm * 128 + aRow) * K + aCol;

    float acc[8][8];
#pragma unroll
    for (int i = 0; i < 8; i++)
#pragma unroll
        for (int j = 0; j < 8; j++) acc[i][j] = 0.f;

    for (int k0 = 0; k0 < K; k0 += 8) {
        float4 av = *(const float4*)(Ab + k0);
        As[aCol + 0][aRow] = av.x;
        As[aCol + 1][aRow] = av.y;
        As[aCol + 2][aRow] = av.z;
        As[aCol + 3][aRow] = av.w;
        float4 wv = make_float4(0.f, 0.f, 0.f, 0.f);
        if (wcol < N)
            wv = *(const float4*)(W + (size_t)(k0 + bRow) * N + wcol);
        *(float4*)&Bs[bRow][bCol] = wv;
        __syncthreads();
#pragma unroll
        for (int kk = 0; kk < 8; kk++) {
            float4 a0 = *(const float4*)&As[kk][tRow];
            float4 a1 = *(const float4*)&As[kk][tRow + 4];
            float4 b0 = *(const float4*)&Bs[kk][tCol];
            float4 b1 = *(const float4*)&Bs[kk][tCol + 4];
            float av8[8] = {a0.x, a0.y, a0.z, a0.w, a1.x, a1.y, a1.z, a1.w};
            float bv8[8] = {b0.x, b0.y, b0.z, b0.w, b1.x, b1.y, b1.z, b1.w};
#pragma unroll
            for (int i = 0; i < 8; i++)
#pragma unroll
                for (int j = 0; j < 8; j++) acc[i][j] += av8[i] * bv8[j];
        }
        __syncthreads();
    }

#pragma unroll
    for (int i = 0; i < 8; i++) {
        size_t row = (size_t)(bm * 128 + tRow + i);
#pragma unroll
        for (int j = 0; j < 8; j += 4) {
            int col = bn * 128 + tCol + j;
            if (col < N) {
                float4 o;
                o.x = acc[i][j + 0] + bias[col + 0];
                o.y = acc[i][j + 1] + bias[col + 1];
                o.z = acc[i][j + 2] + bias[col + 2];
                o.w = acc[i][j + 3] + bias[col + 3];
                *(float4*)&C[row * N + col] = o;
            }
        }
    }
}

// ---------------------------------------------------------------------------
// per-batch K/V pyramid (layout-agnostic row averaging).
__global__ void downsample_b(const float* __restrict__ k0,
                             const float* __restrict__ v0,
                             float* __restrict__ k1, float* __restrict__ v1,
                             float* __restrict__ k2, float* __restrict__ v2) {
    int z = blockIdx.z;
    int lvl2 = z >> 1;
    int Tout = lvl2 ? 512 : 1024;
    int n = Tout * (DIMC / 4);
    int i = blockIdx.x * blockDim.x + threadIdx.x;
    if (i >= n) return;
    int c4 = i % (DIMC / 4);
    int t  = i / (DIMC / 4);
    const float4* in4 = (const float4*)((z & 1) ? v0 : k0);
    float4* out4 = (float4*)(lvl2 ? ((z & 1) ? v2 : k2) : ((z & 1) ? v1 : k1));
    int t0 = t << (1 + lvl2);
    float4 a = in4[(size_t)t0       * (DIMC / 4) + c4];
    float4 c = in4[(size_t)(t0 + 1) * (DIMC / 4) + c4];
    float4 r;
    if (!lvl2) {
        r.x = 0.5f * (a.x + c.x);
        r.y = 0.5f * (a.y + c.y);
        r.z = 0.5f * (a.z + c.z);
        r.w = 0.5f * (a.w + c.w);
    } else {
        float4 d = in4[(size_t)(t0 + 2) * (DIMC / 4) + c4];
        float4 e = in4[(size_t)(t0 + 3) * (DIMC / 4) + c4];
        r.x = 0.5f * (0.5f * (a.x + c.x) + 0.5f * (d.x + e.x));
        r.y = 0.5f * (0.5f * (a.y + c.y) + 0.5f * (d.y + e.y));
        r.z = 0.5f * (0.5f * (a.z + c.z) + 0.5f * (d.z + e.z));
        r.w = 0.5f * (0.5f * (a.w + c.w) + 0.5f * (d.w + e.w));
    }
    out4[i] = r;
}

// fused transpose + tf32 round for 4 weights.
// z<3 (Wq/Wk/Wv): output COLUMN (row of WT) permuted -> K/V/Q head-interleaved.
// z=3 (Wo): k-dim (column of WT) permuted -> consumes permuted ao directly.
__global__ void transpose_rna4(const float* __restrict__ W0, const float* __restrict__ W1,
                               const float* __restrict__ W2, const float* __restrict__ W3,
                               float* __restrict__ WT) {
    __shared__ float tile[32][33];
    int z  = blockIdx.z;
    const float* W = (z == 0) ? W0 : (z == 1) ? W1 : (z == 2) ? W2 : W3;
    float* WTo = WT + (size_t)z * DIMC * DIMC;
    int k0 = blockIdx.x * 32, n0 = blockIdx.y * 32;
    int tx = threadIdx.x, ty = threadIdx.y;   // 32 x 8
#pragma unroll
    for (int i = ty; i < 32; i += 8)
        tile[i][tx] = rna_tf32(W[(size_t)(k0 + i) * DIMC + n0 + tx]);
    __syncthreads();
#pragma unroll
    for (int i = ty; i < 32; i += 8) {
        int n = n0 + i, k = k0 + tx;
        if (z < 3)
            WTo[(size_t)PERM(n) * DIMC + k] = tile[tx][i];
        else
            WTo[(size_t)n * DIMC + PERM(k)] = tile[tx][i];
    }
}

// ---------------------------------------------------------------------------
// attention for one batch: one warp per (t,h); lane owns interleaved RoPE pair
// at column h*64 + 2*lane (+1). All K/V/Q gathers are float2.
__global__ __launch_bounds__(256) void attn_kernel(
    const float* __restrict__ q, const float* __restrict__ offr,
    const float* __restrict__ kall, const float* __restrict__ vall,
    float* __restrict__ out, int b) {
    int warp = (blockIdx.x * blockDim.x + threadIdx.x) >> 5;
    int lane = threadIdx.x & 31;
    int h = warp % HH;
    int t = warp / HH;
    if (t >= TT) return;

    const float LOG1E4 = 9.210340371976184f;
    float inv_freq = __expf(-(float)lane * (LOG1E4 / 32.0f));

    size_t qbase = ((size_t)(b * TT + t) * DIMC) + h * DHH + 2 * lane;
    float2 qv = *(const float2*)&q[qbase];
    float sq, cq;
    sincosf((float)t * inv_freq, &sq, &cq);
    float q1r = qv.x * cq - qv.y * sq;
    float q2r = qv.x * sq + qv.y * cq;

    float refp = (float)t * (1.0f / (float)(TT - 1));

    float p[LL * KKS];
    float vs1[LL * KKS], vs2[LL * KKS];

    const int TsA[3]     = {2048, 1024, 512};
    const int rowbase[3] = {0, 4096, 6144};
    int offb = ((b * TT + t) * HH + h) * (LL * KKS);

    float idxA[LL * KKS], w1A[LL * KKS];
    int   o0A[LL * KKS], o1A[LL * KKS];
#pragma unroll
    for (int l = 0; l < LL; l++) {
        int Ts = TsA[l];
        float Tm1 = (float)(Ts - 1);
        int lvb = (rowbase[l] + b * Ts) * DIMC + h * DHH + 2 * lane;
#pragma unroll
        for (int k = 0; k < KKS; k++) {
            int li = l * KKS + k;
            float ofv = tanhf(offr[offb + li]) * 0.25f;
            float s = fminf(fmaxf(refp + ofv, 0.f), 1.f);
            float idx = fminf(s * Tm1, Tm1 - 1e-6f);
            int i0 = (int)idx;
            int i1 = min(i0 + 1, Ts - 1);
            idxA[li] = idx;
            w1A[li]  = idx - (float)i0;
            o0A[li]  = lvb + i0 * DIMC;
            o1A[li]  = lvb + i1 * DIMC;
        }
    }

#pragma unroll
    for (int li = 0; li < LL * KKS; li++) {
        float w1 = w1A[li], w0 = 1.f - w1;
        float2 k0 = *(const float2*)(kall + o0A[li]);
        float2 k1 = *(const float2*)(kall + o1A[li]);
        float2 v0 = *(const float2*)(vall + o0A[li]);
        float2 v1 = *(const float2*)(vall + o1A[li]);

        float ks1 = w0 * k0.x + w1 * k1.x;
        float ks2 = w0 * k0.y + w1 * k1.y;
        vs1[li]   = w0 * v0.x + w1 * v1.x;
        vs2[li]   = w0 * v0.y + w1 * v1.y;

        float si, co;
        __sincosf(idxA[li] * inv_freq, &si, &co);
        float kr1 = ks1 * co - ks2 * si;
        float kr2 = ks1 * si + ks2 * co;
        p[li] = q1r * kr1 + q2r * kr2;
    }

#pragma unroll
    for (int d = 16; d > 0; d >>= 1) {
#pragma unroll
        for (int li = 0; li < LL * KKS; li++)
            p[li] += __shfl_xor_sync(0xffffffffu, p[li], d);
    }

    float m = p[0] * 0.125f;
#pragma unroll
    for (int i = 1; i < LL * KKS; i++) m = fmaxf(m, p[i] * 0.125f);
    float den = 0.f;
#pragma unroll
    for (int i = 0; i < LL * KKS; i++) {
        p[i] = __expf(p[i] * 0.125f - m);
        den += p[i];
    }
    float rden = 1.f / den;
    float o1 = 0.f, o2 = 0.f;
#pragma unroll
    for (int i = 0; i < LL * KKS; i++) {
        float a = p[i] * rden;
        o1 += a * vs1[i];
        o2 += a * vs2[i];
    }
    *(float2*)&out[qbase] = make_float2(o1, o2);
}

// ---------------------------------------------------------------------------
extern "C" void kernel_launch(void* const* d_in, const int* in_sizes, int n_in,
                              void* d_out, int out_size) {
    const float* x    = (const float*)d_in[0];
    const float* Wq   = (const float*)d_in[2];
    const float* bq   = (const float*)d_in[3];
    const float* Wk   = (const float*)d_in[4];
    const float* bk   = (const float*)d_in[5];
    const float* Wv   = (const float*)d_in[6];
    const float* bv   = (const float*)d_in[7];
    const float* Woff = (const float*)d_in[8];
    const float* boff = (const float*)d_in[9];
    const float* Wo   = (const float*)d_in[10];
    const float* bo   = (const float*)d_in[11];
    float* out = (float*)d_out;

    float *qg, *offg, *kg, *vg, *aog, *wT;
    cudaGetSymbolAddress((void**)&qg,   g_q);
    cudaGetSymbolAddress((void**)&offg, g_off);
    cudaGetSymbolAddress((void**)&kg,   g_k);
    cudaGetSymbolAddress((void**)&vg,   g_v);
    cudaGetSymbolAddress((void**)&aog,  g_ao);
    cudaGetSymbolAddress((void**)&wT,   g_WqkvoT);

    cudaFuncSetAttribute(gemm_tf32, cudaFuncAttributeMaxDynamicSharedMemorySize,
                         GEMM_SMEM);

    // streams + events for capture-legal fork/join (resources only)
    static cudaStream_t s_b1 = nullptr, s_off = nullptr;
    static cudaEvent_t e_fork = nullptr, e_off = nullptr, e_w = nullptr,
                       e_b1 = nullptr;
    if (s_b1 == nullptr) {
        cudaStreamCreateWithFlags(&s_b1, cudaStreamNonBlocking);
        cudaStreamCreateWithFlags(&s_off, cudaStreamNonBlocking);
        cudaEventCreateWithFlags(&e_fork, cudaEventDisableTiming);
        cudaEventCreateWithFlags(&e_off, cudaEventDisableTiming);
        cudaEventCreateWithFlags(&e_w, cudaEventDisableTiming);
        cudaEventCreateWithFlags(&e_b1, cudaEventDisableTiming);
    }

    // fork point
    cudaEventRecord(e_fork, 0);
    cudaStreamWaitEvent(s_off, e_fork, 0);
    cudaStreamWaitEvent(s_b1, e_fork, 0);

    // offset stream: exact fp32 projection for BOTH batches
    {
        dim3 grid(2, (BB * TT) / 128);
        sgemm_bias<<<grid, 256, 0, s_off>>>(BB * TT, HH * LL * KKS, DIMC,
                                            x, Woff, boff, offg);
        cudaEventRecord(e_off, s_off);
    }

    // main (b0) stream: weights first
    transpose_rna4<<<dim3(32, 32, 4), dim3(32, 8)>>>(Wq, Wk, Wv, Wo, wT);
    cudaEventRecord(e_w, 0);
    cudaStreamWaitEvent(s_b1, e_w, 0);

    const size_t bstride = (size_t)TT * DIMC;
    for (int b = 0; b < 2; b++) {
        cudaStream_t st = (b == 0) ? (cudaStream_t)0 : s_b1;
        const float* xb = x + b * bstride;
        float* qb = qg + b * bstride;
        float* kb = kg + b * bstride;
        float* vb = vg + b * bstride;
        float* ab = aog + b * bstride;
        float* ob = out + b * bstride;

        // QKV projection for this batch (permuted bias indexing)
        gemm_tf32<<<dim3(24, 16), 128, GEMM_SMEM, st>>>(
            xb, wT, bq, bk, bv, qb, kb, vb, 1);

        // pyramid for this batch
        {
            float* k1 = kg + ((size_t)4096 + b * 1024) * DIMC;
            float* v1 = vg + ((size_t)4096 + b * 1024) * DIMC;
            float* k2 = kg + ((size_t)6144 + b * 512) * DIMC;
            float* v2 = vg + ((size_t)6144 + b * 512) * DIMC;
            int blocks = (1024 * (DIMC / 4) + 255) / 256;
            downsample_b<<<dim3(blocks, 1, 4), 256, 0, st>>>(
                kb, vb, k1, v1, k2, v2);
        }

        // attention needs offsets
        cudaStreamWaitEvent(st, e_off, 0);
        {
            int warps = TT * HH;
            attn_kernel<<<warps / 8, 256, 0, st>>>(qg, offg, kg, vg, aog, b);
        }

        // output projection (Wo consumes permuted ao; plain bias)
        gemm_tf32<<<dim3(8, 16), 128, GEMM_SMEM, st>>>(
            ab, wT + (size_t)3 * DIMC * DIMC, bo, bo, bo, ob, ob, ob, 0);
    }

    cudaEventRecord(e_b1, s_b1);
    cudaStreamWaitEvent(0, e_b1, 0);
}

// round 16
// speedup vs baseline: 1.5713x; 1.0457x over previous
#include <cuda_runtime.h>
#include <math.h>
#include <stdint.h>

// ---------------------------------------------------------------------------
// Problem constants (fixed by setup_inputs)
#define BB   2
#define TT   2048
#define DIMC 1024
#define HH   16
#define DHH  64
#define LL   3
#define KKS  4
#define TOTROWS 7168           // 4096 + 2048 + 1024 rows of K/V

// GEMM tiling: 128x128 CTA tile, BK=32, 3-stage cp.async, 4 warps (64x64 each)
#define BM 128
#define BN 128
#define BK 32
#define NSTAGE 3
#define NT (DIMC / BK)          // 32 k-iterations
#define ROWF 36                 // smem row stride in floats (144B)
#define TILEF (BM * ROWF)
#define STAGEF (2 * TILEF)
#define GEMM_SMEM (NSTAGE * STAGEF * 4)   // 110592 bytes -> 2 CTAs/SM

// Head-dim interleave permutation: old col d = h*64 + s*32 + j  (s in {0,1})
//   -> new position h*64 + 2*j + s.  RoPE pair (j, j+32) becomes adjacent.
#define PERM(d) (((d) & ~63) | ((((d) & 31) << 1) | (((d) >> 5) & 1)))

// ---------------------------------------------------------------------------
// scratch (device globals; no allocation allowed)
__device__ float g_q     [BB * TT * DIMC];
__device__ float g_off   [BB * TT * HH * LL * KKS];
__device__ float g_k     [TOTROWS * DIMC];
__device__ float g_v     [TOTROWS * DIMC];
__device__ float g_ao    [BB * TT * DIMC];
__device__ float g_WqkvoT[4 * DIMC * DIMC];          // [Wq;Wk;Wv;Wo] transposed [N,K]

// ---------------------------------------------------------------------------
__device__ __forceinline__ float rna_tf32(float x) {
    float r;
    asm("cvt.rna.tf32.f32 %0, %1;" : "=f"(r) : "f"(x));
    return r;
}
__device__ __forceinline__ uint32_t rna_tf32_u(uint32_t x) {
    uint32_t r;
    asm("cvt.rna.tf32.f32 %0, %1;" : "=r"(r) : "r"(x));
    return r;
}
__device__ __forceinline__ uint32_t smem_u32(const void* p) {
    uint32_t a;
    asm("{ .reg .u64 t; cvta.to.shared.u64 t, %1; cvt.u32.u64 %0, t; }"
        : "=r"(a) : "l"(p));
    return a;
}
__device__ __forceinline__ void cp_async16(uint32_t dst, const void* src) {
    asm volatile("cp.async.cg.shared.global [%0], [%1], 16;"
                 :: "r"(dst), "l"(src) : "memory");
}
__device__ __forceinline__ void cp_commit() {
    asm volatile("cp.async.commit_group;" ::: "memory");
}
template <int N>
__device__ __forceinline__ void cp_wait() {
    asm volatile("cp.async.wait_group %0;" :: "n"(N) : "memory");
}
__device__ __forceinline__ void ldsm_x4(uint32_t& r0, uint32_t& r1,
                                        uint32_t& r2, uint32_t& r3, uint32_t addr) {
    asm volatile("ldmatrix.sync.aligned.m8n8.x4.shared.b16 {%0,%1,%2,%3}, [%4];"
                 : "=r"(r0), "=r"(r1), "=r"(r2), "=r"(r3) : "r"(addr));
}
__device__ __forceinline__ void mma_tf32(float& d0, float& d1, float& d2, float& d3,
                                         uint32_t a0, uint32_t a1, uint32_t a2, uint32_t a3,
                                         uint32_t b0, uint32_t b1) {
    asm volatile(
        "mma.sync.aligned.m16n8k8.row.col.f32.tf32.tf32.f32 "
        "{%0,%1,%2,%3}, {%4,%5,%6,%7}, {%8,%9}, {%0,%1,%2,%3};"
        : "+f"(d0), "+f"(d1), "+f"(d2), "+f"(d3)
        : "r"(a0), "r"(a1), "r"(a2), "r"(a3), "r"(b0), "r"(b1));
}

// ---------------------------------------------------------------------------
// tf32 mma.sync GEMM, 128x128 tile, 4 warps (2x2, 64x64 warp tiles),
// ldmatrix + in-register RN rounding of A, segmented output routing.
__global__ __launch_bounds__(128, 2) void gemm_tf32(
    const float* __restrict__ A, const float* __restrict__ BT,
    const float* __restrict__ b0, const float* __restrict__ b1,
    const float* __restrict__ b2,
    float* __restrict__ C0, float* __restrict__ C1, float* __restrict__ C2,
    int permb) {
    extern __shared__ float smem[];

    int tid  = threadIdx.x;
    int wid  = tid >> 5, lane = tid & 31;
    int gid  = lane >> 2, tg = lane & 3;
    int wm   = wid >> 1;
    int wn   = wid & 1;
    int m0   = blockIdx.y * BM;

    int seg  = blockIdx.x >> 3;
    int ncol = (blockIdx.x & 7) * BN;
    const float* bias = (seg == 0) ? b0 : (seg == 1) ? b1 : b2;
    float* C          = (seg == 0) ? C0 : (seg == 1) ? C1 : C2;

    uint32_t sbase = smem_u32(smem);

    const float* Abase = A  + (size_t)m0 * DIMC;
    const float* Bbase = BT + (size_t)blockIdx.x * BN * DIMC;

    int lrow = lane & 7;
    int lm8  = (lane >> 3) & 1;
    int lk4  = (lane >> 4) & 1;
    uint32_t a_off[4];
#pragma unroll
    for (int mi = 0; mi < 4; mi++) {
        int row = wm * 64 + mi * 16 + lm8 * 8 + lrow;
        a_off[mi] = (uint32_t)((row * ROWF + lk4 * 4) * 4);
    }
    uint32_t bt_off[4];
#pragma unroll
    for (int p = 0; p < 4; p++) {
        int n = wn * 64 + p * 16 + lk4 * 8 + lrow;
        bt_off[p] = (uint32_t)((n * ROWF + lm8 * 4) * 4);
    }

    float acc[4][8][4];
#pragma unroll
    for (int mi = 0; mi < 4; mi++)
#pragma unroll
        for (int ni = 0; ni < 8; ni++)
#pragma unroll
            for (int r = 0; r < 4; r++) acc[mi][ni][r] = 0.f;

#define ISSUE_STAGE(pt) do {                                                   \
        uint32_t sa_  = sbase + (((pt) % NSTAGE) * STAGEF) * 4;                \
        uint32_t sbB_ = sa_ + TILEF * 4;                                       \
        _Pragma("unroll")                                                      \
        for (int i_ = 0; i_ < 8; i_++) {                                       \
            int cid_ = i_ * 128 + tid;                                         \
            int r_ = cid_ >> 3, c_ = cid_ & 7;                                 \
            cp_async16(sa_ + (r_ * ROWF + c_ * 4) * 4,                         \
                       Abase + (size_t)r_ * DIMC + (pt) * BK + c_ * 4);        \
            cp_async16(sbB_ + (r_ * ROWF + c_ * 4) * 4,                        \
                       Bbase + (size_t)r_ * DIMC + (pt) * BK + c_ * 4);        \
        }                                                                      \
        cp_commit();                                                           \
    } while (0)

    ISSUE_STAGE(0);
    ISSUE_STAGE(1);

    for (int kt = 0; kt < NT; kt++) {
        if (kt + 2 < NT) cp_wait<1>(); else cp_wait<0>();
        __syncthreads();

        if (kt + 2 < NT) ISSUE_STAGE(kt + 2);

        uint32_t abase = sbase + ((kt % NSTAGE) * STAGEF) * 4;
        uint32_t bbase = abase + TILEF * 4;

#pragma unroll
        for (int j = 0; j < 4; j++) {
            uint32_t af[4][4], bf[8][2];
            uint32_t jb = (uint32_t)(j * 32);
#pragma unroll
            for (int mi = 0; mi < 4; mi++) {
                ldsm_x4(af[mi][0], af[mi][1], af[mi][2], af[mi][3],
                        abase + a_off[mi] + jb);
                af[mi][0] = rna_tf32_u(af[mi][0]);
                af[mi][1] = rna_tf32_u(af[mi][1]);
                af[mi][2] = rna_tf32_u(af[mi][2]);
                af[mi][3] = rna_tf32_u(af[mi][3]);
            }
#pragma unroll
            for (int p = 0; p < 4; p++)
                ldsm_x4(bf[2 * p][0], bf[2 * p][1], bf[2 * p + 1][0],
                        bf[2 * p + 1][1], bbase + bt_off[p] + jb);
#pragma unroll
            for (int mi = 0; mi < 4; mi++)
#pragma unroll
                for (int ni = 0; ni < 8; ni++)
                    mma_tf32(acc[mi][ni][0], acc[mi][ni][1],
                             acc[mi][ni][2], acc[mi][ni][3],
                             af[mi][0], af[mi][1], af[mi][2], af[mi][3],
                             bf[ni][0], bf[ni][1]);
        }
    }

#pragma unroll
    for (int mi = 0; mi < 4; mi++) {
        int r0 = m0 + wm * 64 + mi * 16 + gid;
#pragma unroll
        for (int ni = 0; ni < 8; ni++) {
            int c = ncol + wn * 64 + ni * 8 + tg * 2;   // even
            float bx, by;
            if (permb) {
                int hbase = c & ~63;
                int jj = (c & 63) >> 1;
                bx = bias[hbase + jj];
                by = bias[hbase + 32 + jj];
            } else {
                bx = bias[c];
                by = bias[c + 1];
            }
            float2 o0 = make_float2(acc[mi][ni][0] + bx, acc[mi][ni][1] + by);
            float2 o1 = make_float2(acc[mi][ni][2] + bx, acc[mi][ni][3] + by);
            *(float2*)&C[(size_t)r0 * DIMC + c] = o0;
            *(float2*)&C[(size_t)(r0 + 8) * DIMC + c] = o1;
        }
    }
#undef ISSUE_STAGE
}

// ---------------------------------------------------------------------------
// fp32 SGEMM (exact) for the offset projection: C[M,N] = A@W + bias, N=192
__global__ __launch_bounds__(256) void sgemm_bias(
    int M, int N, int K,
    const float* __restrict__ A, const float* __restrict__ W,
    const float* __restrict__ bias, float* __restrict__ C) {
    __shared__ float As[8][128];
    __shared__ float Bs[8][128];

    int tid = threadIdx.x;
    int bm = blockIdx.y, bn = blockIdx.x;

    int aRow = tid >> 1;
    int aCol = (tid & 1) * 4;
    int bRow = tid >> 5;
    int bCol = (tid & 31) * 4;
    int wcol = bn * 128 + bCol;

    int tRow = (tid >> 4) * 8;
    int tCol = (tid & 15) * 8;

    const float* Ab = A + (size_t)(bm * 128 + aRow) * K + aCol;

    float acc[8][8];
#pragma unroll
    for (int i = 0; i < 8; i++)
#pragma unroll
        for (int j = 0; j < 8; j++) acc[i][j] = 0.f;

    for (int k0 = 0; k0 < K; k0 += 8) {
        float4 av = *(const float4*)(Ab + k0);
        As[aCol + 0][aRow] = av.x;
        As[aCol + 1][aRow] = av.y;
        As[aCol + 2][aRow] = av.z;
        As[aCol + 3][aRow] = av.w;
        float4 wv = make_float4(0.f, 0.f, 0.f, 0.f);
        if (wcol < N)
            wv = *(const float4*)(W + (size_t)(k0 + bRow) * N + wcol);
        *(float4*)&Bs[bRow][bCol] = wv;
        __syncthreads();
#pragma unroll
        for (int kk = 0; kk < 8; kk++) {
            float4 a0 = *(const float4*)&As[kk][tRow];
            float4 a1 = *(const float4*)&As[kk][tRow + 4];
            float4 b0 = *(const float4*)&Bs[kk][tCol];
            float4 b1 = *(const float4*)&Bs[kk][tCol + 4];
            float av8[8] = {a0.x, a0.y, a0.z, a0.w, a1.x, a1.y, a1.z, a1.w};
            float bv8[8] = {b0.x, b0.y, b0.z, b0.w, b1.x, b1.y, b1.z, b1.w};
#pragma unroll
            for (int i = 0; i < 8; i++)
#pragma unroll
                for (int j = 0; j < 8; j++) acc[i][j] += av8[i] * bv8[j];
        }
        __syncthreads();
    }

#pragma unroll
    for (int i = 0; i < 8; i++) {
        size_t row = (size_t)(bm * 128 + tRow + i);
#pragma unroll
        for (int j = 0; j < 8; j += 4) {
            int col = bn * 128 + tCol + j;
            if (col < N) {
                float4 o;
                o.x = acc[i][j + 0] + bias[col + 0];
                o.y = acc[i][j + 1] + bias[col + 1];
                o.z = acc[i][j + 2] + bias[col + 2];
                o.w = acc[i][j + 3] + bias[col + 3];
                *(float4*)&C[row * N + col] = o;
            }
        }
    }
}

// ---------------------------------------------------------------------------
// per-batch K/V pyramid (layout-agnostic row averaging).
__global__ void downsample_b(const float* __restrict__ k0,
                             const float* __restrict__ v0,
                             float* __restrict__ k1, float* __restrict__ v1,
                             float* __restrict__ k2, float* __restrict__ v2) {
    int z = blockIdx.z;
    int lvl2 = z >> 1;
    int Tout = lvl2 ? 512 : 1024;
    int n = Tout * (DIMC / 4);
    int i = blockIdx.x * blockDim.x + threadIdx.x;
    if (i >= n) return;
    int c4 = i % (DIMC / 4);
    int t  = i / (DIMC / 4);
    const float4* in4 = (const float4*)((z & 1) ? v0 : k0);
    float4* out4 = (float4*)(lvl2 ? ((z & 1) ? v2 : k2) : ((z & 1) ? v1 : k1));
    int t0 = t << (1 + lvl2);
    float4 a = in4[(size_t)t0       * (DIMC / 4) + c4];
    float4 c = in4[(size_t)(t0 + 1) * (DIMC / 4) + c4];
    float4 r;
    if (!lvl2) {
        r.x = 0.5f * (a.x + c.x);
        r.y = 0.5f * (a.y + c.y);
        r.z = 0.5f * (a.z + c.z);
        r.w = 0.5f * (a.w + c.w);
    } else {
        float4 d = in4[(size_t)(t0 + 2) * (DIMC / 4) + c4];
        float4 e = in4[(size_t)(t0 + 3) * (DIMC / 4) + c4];
        r.x = 0.5f * (0.5f * (a.x + c.x) + 0.5f * (d.x + e.x));
        r.y = 0.5f * (0.5f * (a.y + c.y) + 0.5f * (d.y + e.y));
        r.z = 0.5f * (0.5f * (a.z + c.z) + 0.5f * (d.z + e.z));
        r.w = 0.5f * (0.5f * (a.w + c.w) + 0.5f * (d.w + e.w));
    }
    out4[i] = r;
}

// fused transpose + tf32 round for 4 weights (head-interleave permuted).
__global__ void transpose_rna4(const float* __restrict__ W0, const float* __restrict__ W1,
                               const float* __restrict__ W2, const float* __restrict__ W3,
                               float* __restrict__ WT) {
    __shared__ float tile[32][33];
    int z  = blockIdx.z;
    const float* W = (z == 0) ? W0 : (z == 1) ? W1 : (z == 2) ? W2 : W3;
    float* WTo = WT + (size_t)z * DIMC * DIMC;
    int k0 = blockIdx.x * 32, n0 = blockIdx.y * 32;
    int tx = threadIdx.x, ty = threadIdx.y;   // 32 x 8
#pragma unroll
    for (int i = ty; i < 32; i += 8)
        tile[i][tx] = rna_tf32(W[(size_t)(k0 + i) * DIMC + n0 + tx]);
    __syncthreads();
#pragma unroll
    for (int i = ty; i < 32; i += 8) {
        int n = n0 + i, k = k0 + tx;
        if (z < 3)
            WTo[(size_t)PERM(n) * DIMC + k] = tile[tx][i];
        else
            WTo[(size_t)n * DIMC + PERM(k)] = tile[tx][i];
    }
}

// ---------------------------------------------------------------------------
// attention: half-warp per (t,h). Lane owns dims 4*hl..4*hl+3 of its head
// (interleaved pairs 2*hl, 2*hl+1). All gathers are float4.
__global__ __launch_bounds__(128) void attn_kernel(
    const float* __restrict__ q, const float* __restrict__ offr,
    const float* __restrict__ kall, const float* __restrict__ vall,
    float* __restrict__ out, int b) {
    int warp = (blockIdx.x * blockDim.x + threadIdx.x) >> 5;
    int lane = threadIdx.x & 31;
    int hp = warp % (HH / 2);
    int t  = warp / (HH / 2);
    if (t >= TT) return;
    int h  = hp * 2 + (lane >> 4);   // per-half-warp head
    int hl = lane & 15;

    const float LOG1E4 = 9.210340371976184f;
    float j0  = (float)(2 * hl);
    float if0 = __expf(-j0 * (LOG1E4 / 32.0f));
    float if1 = __expf(-(j0 + 1.0f) * (LOG1E4 / 32.0f));

    size_t qbase = ((size_t)(b * TT + t) * DIMC) + h * DHH + 4 * hl;
    float4 qv = *(const float4*)&q[qbase];
    float s0, c0, s1, c1;
    sincosf((float)t * if0, &s0, &c0);
    sincosf((float)t * if1, &s1, &c1);
    float q1r = qv.x * c0 - qv.y * s0, q2r = qv.x * s0 + qv.y * c0;
    float q3r = qv.z * c1 - qv.w * s1, q4r = qv.z * s1 + qv.w * c1;

    float refp = (float)t * (1.0f / (float)(TT - 1));

    float p[LL * KKS];
    float4 vsv[LL * KKS];

    const int TsA[3]     = {2048, 1024, 512};
    const int rowbase[3] = {0, 4096, 6144};
    int offb = ((b * TT + t) * HH + h) * (LL * KKS);

    float idxA[LL * KKS], w1A[LL * KKS];
    int   o0A[LL * KKS], o1A[LL * KKS];
#pragma unroll
    for (int l = 0; l < LL; l++) {
        int Ts = TsA[l];
        float Tm1 = (float)(Ts - 1);
        int lvb = (rowbase[l] + b * Ts) * DIMC + h * DHH + 4 * hl;
#pragma unroll
        for (int k = 0; k < KKS; k++) {
            int li = l * KKS + k;
            float ofv = tanhf(offr[offb + li]) * 0.25f;
            float s = fminf(fmaxf(refp + ofv, 0.f), 1.f);
            float idx = fminf(s * Tm1, Tm1 - 1e-6f);
            int i0 = (int)idx;
            int i1 = min(i0 + 1, Ts - 1);
            idxA[li] = idx;
            w1A[li]  = idx - (float)i0;
            o0A[li]  = lvb + i0 * DIMC;
            o1A[li]  = lvb + i1 * DIMC;
        }
    }

#pragma unroll
    for (int li = 0; li < LL * KKS; li++) {
        float w1 = w1A[li], w0 = 1.f - w1;
        float4 k0 = *(const float4*)(kall + o0A[li]);
        float4 k1 = *(const float4*)(kall + o1A[li]);
        float4 v0 = *(const float4*)(vall + o0A[li]);
        float4 v1 = *(const float4*)(vall + o1A[li]);

        float ks1 = w0 * k0.x + w1 * k1.x;
        float ks2 = w0 * k0.y + w1 * k1.y;
        float ks3 = w0 * k0.z + w1 * k1.z;
        float ks4 = w0 * k0.w + w1 * k1.w;
        vsv[li].x = w0 * v0.x + w1 * v1.x;
        vsv[li].y = w0 * v0.y + w1 * v1.y;
        vsv[li].z = w0 * v0.z + w1 * v1.z;
        vsv[li].w = w0 * v0.w + w1 * v1.w;

        float si0, co0, si1, co1;
        __sincosf(idxA[li] * if0, &si0, &co0);
        __sincosf(idxA[li] * if1, &si1, &co1);
        float kr1 = ks1 * co0 - ks2 * si0;
        float kr2 = ks1 * si0 + ks2 * co0;
        float kr3 = ks3 * co1 - ks4 * si1;
        float kr4 = ks3 * si1 + ks4 * co1;
        p[li] = q1r * kr1 + q2r * kr2 + q3r * kr3 + q4r * kr4;
    }

    // reduce within each 16-lane half-warp
#pragma unroll
    for (int d = 8; d > 0; d >>= 1) {
#pragma unroll
        for (int li = 0; li < LL * KKS; li++)
            p[li] += __shfl_xor_sync(0xffffffffu, p[li], d);
    }

    float m = p[0] * 0.125f;
#pragma unroll
    for (int i = 1; i < LL * KKS; i++) m = fmaxf(m, p[i] * 0.125f);
    float den = 0.f;
#pragma unroll
    for (int i = 0; i < LL * KKS; i++) {
        p[i] = __expf(p[i] * 0.125f - m);
        den += p[i];
    }
    float rden = 1.f / den;
    float4 o = make_float4(0.f, 0.f, 0.f, 0.f);
#pragma unroll
    for (int i = 0; i < LL * KKS; i++) {
        float a = p[i] * rden;
        o.x += a * vsv[i].x;
        o.y += a * vsv[i].y;
        o.z += a * vsv[i].z;
        o.w += a * vsv[i].w;
    }
    *(float4*)&out[qbase] = o;
}

// ---------------------------------------------------------------------------
extern "C" void kernel_launch(void* const* d_in, const int* in_sizes, int n_in,
                              void* d_out, int out_size) {
    const float* x    = (const float*)d_in[0];
    const float* Wq   = (const float*)d_in[2];
    const float* bq   = (const float*)d_in[3];
    const float* Wk   = (const float*)d_in[4];
    const float* bk   = (const float*)d_in[5];
    const float* Wv   = (const float*)d_in[6];
    const float* bv   = (const float*)d_in[7];
    const float* Woff = (const float*)d_in[8];
    const float* boff = (const float*)d_in[9];
    const float* Wo   = (const float*)d_in[10];
    const float* bo   = (const float*)d_in[11];
    float* out = (float*)d_out;

    float *qg, *offg, *kg, *vg, *aog, *wT;
    cudaGetSymbolAddress((void**)&qg,   g_q);
    cudaGetSymbolAddress((void**)&offg, g_off);
    cudaGetSymbolAddress((void**)&kg,   g_k);
    cudaGetSymbolAddress((void**)&vg,   g_v);
    cudaGetSymbolAddress((void**)&aog,  g_ao);
    cudaGetSymbolAddress((void**)&wT,   g_WqkvoT);

    cudaFuncSetAttribute(gemm_tf32, cudaFuncAttributeMaxDynamicSharedMemorySize,
                         GEMM_SMEM);

    // streams + events for capture-legal fork/join (resources only)
    static cudaStream_t s_b1 = nullptr, s_off = nullptr;
    static cudaEvent_t e_fork = nullptr, e_off = nullptr, e_w = nullptr,
                       e_b1 = nullptr;
    if (s_b1 == nullptr) {
        cudaStreamCreateWithFlags(&s_b1, cudaStreamNonBlocking);
        cudaStreamCreateWithFlags(&s_off, cudaStreamNonBlocking);
        cudaEventCreateWithFlags(&e_fork, cudaEventDisableTiming);
        cudaEventCreateWithFlags(&e_off, cudaEventDisableTiming);
        cudaEventCreateWithFlags(&e_w, cudaEventDisableTiming);
        cudaEventCreateWithFlags(&e_b1, cudaEventDisableTiming);
    }

    // fork point
    cudaEventRecord(e_fork, 0);
    cudaStreamWaitEvent(s_off, e_fork, 0);
    cudaStreamWaitEvent(s_b1, e_fork, 0);

    // offset stream: exact fp32 projection for BOTH batches
    {
        dim3 grid(2, (BB * TT) / 128);
        sgemm_bias<<<grid, 256, 0, s_off>>>(BB * TT, HH * LL * KKS, DIMC,
                                            x, Woff, boff, offg);
        cudaEventRecord(e_off, s_off);
    }

    // main (b0) stream: weights first
    transpose_rna4<<<dim3(32, 32, 4), dim3(32, 8)>>>(Wq, Wk, Wv, Wo, wT);
    cudaEventRecord(e_w, 0);
    cudaStreamWaitEvent(s_b1, e_w, 0);

    const size_t bstride = (size_t)TT * DIMC;
    for (int b = 0; b < 2; b++) {
        cudaStream_t st = (b == 0) ? (cudaStream_t)0 : s_b1;
        const float* xb = x + b * bstride;
        float* qb = qg + b * bstride;
        float* kb = kg + b * bstride;
        float* vb = vg + b * bstride;
        float* ab = aog + b * bstride;
        float* ob = out + b * bstride;

        // QKV projection for this batch (permuted bias indexing)
        gemm_tf32<<<dim3(24, 16), 128, GEMM_SMEM, st>>>(
            xb, wT, bq, bk, bv, qb, kb, vb, 1);

        // pyramid for this batch
        {
            float* k1 = kg + ((size_t)4096 + b * 1024) * DIMC;
            float* v1 = vg + ((size_t)4096 + b * 1024) * DIMC;
            float* k2 = kg + ((size_t)6144 + b * 512) * DIMC;
            float* v2 = vg + ((size_t)6144 + b * 512) * DIMC;
            int blocks = (1024 * (DIMC / 4) + 255) / 256;
            downsample_b<<<dim3(blocks, 1, 4), 256, 0, st>>>(
                kb, vb, k1, v1, k2, v2);
        }

        // attention needs offsets
        cudaStreamWaitEvent(st, e_off, 0);
        {
            int warps = TT * (HH / 2);        // 16384 per batch
            attn_kernel<<<warps / 4, 128, 0, st>>>(qg, offg, kg, vg, aog, b);
        }

        // output projection (Wo consumes permuted ao; plain bias)
        gemm_tf32<<<dim3(8, 16), 128, GEMM_SMEM, st>>>(
            ab, wT + (size_t)3 * DIMC * DIMC, bo, bo, bo, ob, ob, ob, 0);
    }

    cudaEventRecord(e_b1, s_b1);
    cudaStreamWaitEvent(0, e_b1, 0);
}